// round 9
// baseline (speedup 1.0000x reference)
#include <cuda_runtime.h>
#include <cuda_bf16.h>
#include <math.h>
#include <stdint.h>

#define BATCH 2
#define SEQ 1024
#define HEADS 32
#define DHEAD 64
#define DM 2048
#define MTOK (BATCH * SEQ)      // 2048
#define NGROUPS 22
#define NELEM ((size_t)DM * DM) // 4194304

// ---------------- scratch (device globals; no allocation allowed) ----------
__device__ float g_Q[(size_t)MTOK * DM];
__device__ float g_K[(size_t)MTOK * DM];
__device__ float g_V[(size_t)MTOK * DM];

__device__ __nv_bfloat16 g_xh[NELEM], g_xl[NELEM];
__device__ __nv_bfloat16 g_oh[NELEM], g_ol[NELEM];      // attn output bf16 hi/lo
__device__ __nv_bfloat16 g_wqh[NELEM], g_wql[NELEM];
__device__ __nv_bfloat16 g_woh[NELEM], g_wol[NELEM];
__device__ __nv_bfloat16 g_kbh[NELEM], g_kbl[NELEM];    // K (post-quant) [b*S+s][h*64+d]
__device__ __nv_bfloat16 g_vth[NELEM], g_vtl[NELEM];    // V^T [(b*H+h)*64+d][s]

// ---------------- helpers ---------------------------------------------------
__device__ __forceinline__ uint32_t smem_u32(const void* p) {
    uint32_t a;
    asm("{ .reg .u64 t; cvta.to.shared.u64 t, %1; cvt.u32.u64 %0, t; }"
        : "=r"(a) : "l"(p));
    return a;
}
__device__ __forceinline__ void ldsm4(uint32_t* r, uint32_t addr) {
    asm volatile("ldmatrix.sync.aligned.m8n8.x4.shared.b16 {%0,%1,%2,%3}, [%4];"
                 : "=r"(r[0]), "=r"(r[1]), "=r"(r[2]), "=r"(r[3]) : "r"(addr));
}
__device__ __forceinline__ void mma16816(float* d, const uint32_t* a, const uint32_t* b) {
    asm volatile(
        "mma.sync.aligned.m16n8k16.row.col.f32.bf16.bf16.f32 "
        "{%0,%1,%2,%3}, {%4,%5,%6,%7}, {%8,%9}, {%0,%1,%2,%3};"
        : "+f"(d[0]), "+f"(d[1]), "+f"(d[2]), "+f"(d[3])
        : "r"(a[0]), "r"(a[1]), "r"(a[2]), "r"(a[3]), "r"(b[0]), "r"(b[1]));
}
__device__ __forceinline__ void cp16(uint32_t s, const void* g) {
    uint64_t ga = __cvta_generic_to_global(g);
    asm volatile("cp.async.cg.shared.global [%0], [%1], 16;" :: "r"(s), "l"(ga));
}
__device__ __forceinline__ void cp_commit() {
    asm volatile("cp.async.commit_group;" ::: "memory");
}
template <int N>
__device__ __forceinline__ void cp_wait() {
    asm volatile("cp.async.wait_group %0;" :: "n"(N) : "memory");
}
__device__ __forceinline__ uint32_t pack2bf(float x, float y) {
    __nv_bfloat162 t = __floats2bfloat162_rn(x, y);
    return *(uint32_t*)&t;
}
__device__ __forceinline__ float bfres(float x) {
    return x - __bfloat162float(__float2bfloat16(x));
}
__device__ __forceinline__ void fma_f32x2(uint64_t& d, uint64_t a, uint64_t b) {
    asm("fma.rn.f32x2 %0, %1, %2, %0;" : "+l"(d) : "l"(a), "l"(b));
}

// ---------------------------------------------------------------------------
// fp32 SGEMM (K,V; numerics-critical; bit-identical FFMA chain).
// Duplicated-A smem layout: LDS.64 loads the (a,a) pair directly.
// ---------------------------------------------------------------------------
#define BM 128
#define BN 128
#define TM 8
#define TN 8
#define S2_BK 16
#define SG_SMEM ((2 * S2_BK * 2 * BM + 2 * S2_BK * BN) * 4)   // 49152 B

__global__ __launch_bounds__(256, 2) void sgemm_nn(
    const float* __restrict__ A, const float* __restrict__ B,
    float* __restrict__ C, int M, int N, int K)
{
    extern __shared__ float smf[];
    float* As2 = smf;                         // [2][S2_BK][256] duplicated
    float* BsD = smf + 2 * S2_BK * 2 * BM;    // [2][S2_BK][128]

    const int tid = threadIdx.x;
    const int block_row = blockIdx.y * BM;
    const int block_col = blockIdx.x * BN;

    const int am = tid >> 1;
    const int ak = (tid & 1) * 8;
    const int bk0 = tid >> 5;
    const int bn0 = (tid & 31) * 4;
    const int tr = (tid >> 4) * TM;
    const int tc = (tid & 15) * TN;

    const uint32_t bs_base = smem_u32(BsD);

    uint64_t acc2[TM][TN / 2];
    #pragma unroll
    for (int i = 0; i < TM; i++)
        #pragma unroll
        for (int j = 0; j < TN / 2; j++) acc2[i][j] = 0ull;

    float a0[8];
    auto ldgA = [&](int c) {
        float4 u = *(const float4*)&A[(size_t)(block_row + am) * K + c * S2_BK + ak];
        float4 v = *(const float4*)&A[(size_t)(block_row + am) * K + c * S2_BK + ak + 4];
        a0[0] = u.x; a0[1] = u.y; a0[2] = u.z; a0[3] = u.w;
        a0[4] = v.x; a0[5] = v.y; a0[6] = v.z; a0[7] = v.w;
    };
    auto stsA = [&](int buf) {
        #pragma unroll
        for (int i = 0; i < 8; i++) {
            float* d = As2 + ((buf * S2_BK + ak + i) * 2 * BM) + 2 * am;
            d[0] = a0[i];
            d[1] = a0[i];
        }
    };
    auto cpB = [&](int c, int buf) {
        cp16(bs_base + (uint32_t)((buf * S2_BK + bk0) * BN + bn0) * 4,
             &B[(size_t)(c * S2_BK + bk0) * N + block_col + bn0]);
        cp16(bs_base + (uint32_t)((buf * S2_BK + bk0 + 8) * BN + bn0) * 4,
             &B[(size_t)(c * S2_BK + bk0 + 8) * N + block_col + bn0]);
    };

    const int NCH = K / S2_BK;
    ldgA(0);
    cpB(0, 0);
    cp_commit();
    stsA(0);

    for (int c = 0; c < NCH; c++) {
        const int buf = c & 1;
        if (c + 1 < NCH) {
            ldgA(c + 1);
            cpB(c + 1, buf ^ 1);
            cp_commit();
            cp_wait<1>();
        } else {
            cp_wait<0>();
        }
        __syncthreads();

        #pragma unroll
        for (int kk = 0; kk < S2_BK; kk++) {
            const float* arow = As2 + ((buf * S2_BK + kk) * 2 * BM);
            const float* brow = BsD + ((buf * S2_BK + kk) * BN);
            uint64_t a2[TM], b2[TN / 2];
            #pragma unroll
            for (int i = 0; i < TM; i++)
                a2[i] = *(const uint64_t*)&arow[2 * (tr + i)];
            #pragma unroll
            for (int j = 0; j < TN / 2; j++)
                b2[j] = *(const uint64_t*)&brow[tc + 2 * j];
            #pragma unroll
            for (int i = 0; i < TM; i++)
                #pragma unroll
                for (int j = 0; j < TN / 2; j++)
                    fma_f32x2(acc2[i][j], a2[i], b2[j]);
        }
        if (c + 1 < NCH) stsA(buf ^ 1);
        __syncthreads();
    }

    #pragma unroll
    for (int i = 0; i < TM; i++) {
        float cvals[TN];
        #pragma unroll
        for (int j = 0; j < TN / 2; j++) {
            float lo, hi;
            asm("mov.b64 {%0, %1}, %2;" : "=f"(lo), "=f"(hi) : "l"(acc2[i][j]));
            cvals[2 * j] = lo;
            cvals[2 * j + 1] = hi;
        }
        #pragma unroll
        for (int j = 0; j < TN; j += 4) {
            float4 cv = make_float4(cvals[j], cvals[j+1], cvals[j+2], cvals[j+3]);
            *(float4*)&C[(size_t)(block_row + tr + i) * N + block_col + tc + j] = cv;
        }
    }
}

// ---------------------------------------------------------------------------
// 2-level split and weight transpose-split (unchanged numerics)
// ---------------------------------------------------------------------------
__global__ __launch_bounds__(256) void split_kernel(
    const float* __restrict__ src, __nv_bfloat16* __restrict__ hi,
    __nv_bfloat16* __restrict__ lo)
{
    size_t i = ((size_t)blockIdx.x * 256 + threadIdx.x) * 4;
    float4 v = *(const float4*)(src + i);
    float vv[4] = { v.x, v.y, v.z, v.w };
    __nv_bfloat16 h[4], l[4];
    #pragma unroll
    for (int e = 0; e < 4; e++) {
        h[e] = __float2bfloat16(vv[e]);
        l[e] = __float2bfloat16(vv[e] - __bfloat162float(h[e]));
    }
    *(__nv_bfloat162*)(hi + i)     = { h[0], h[1] };
    *(__nv_bfloat162*)(hi + i + 2) = { h[2], h[3] };
    *(__nv_bfloat162*)(lo + i)     = { l[0], l[1] };
    *(__nv_bfloat162*)(lo + i + 2) = { l[2], l[3] };
}

__global__ __launch_bounds__(256) void tsplit_kernel(
    const float* __restrict__ W, __nv_bfloat16* __restrict__ Th,
    __nv_bfloat16* __restrict__ Tl)
{
    __shared__ float t[32][33];
    const int x = threadIdx.x;
    const int y = threadIdx.y;
    const int n0 = blockIdx.x * 32;
    const int k0 = blockIdx.y * 32;
    #pragma unroll
    for (int i = 0; i < 4; i++)
        t[y + i * 8][x] = W[(size_t)(k0 + y + i * 8) * DM + n0 + x];
    __syncthreads();
    #pragma unroll
    for (int i = 0; i < 4; i++) {
        float v = t[x][y + i * 8];
        __nv_bfloat16 h = __float2bfloat16(v);
        __nv_bfloat16 l = __float2bfloat16(v - __bfloat162float(h));
        size_t o = (size_t)(n0 + y + i * 8) * DM + k0 + x;
        Th[o] = h;
        Tl[o] = l;
    }
}

// Per-(b,h) transpose + split: V[(b*S+s)][h*64+d] -> Vt[(b*H+h)*64+d][s]
__global__ __launch_bounds__(256) void convert_vt_kernel(
    const float* __restrict__ V, __nv_bfloat16* __restrict__ Vh,
    __nv_bfloat16* __restrict__ Vl)
{
    __shared__ float t[32][33];
    const int x = threadIdx.x;
    const int y = threadIdx.y;
    const int s0 = blockIdx.x * 32;
    const int d0 = blockIdx.y * 32;
    const int bh = blockIdx.z;
    const int b = bh >> 5;
    const int h = bh & 31;
    #pragma unroll
    for (int i = 0; i < 4; i++)
        t[y + i * 8][x] = V[(size_t)(b * SEQ + s0 + y + i * 8) * DM + h * DHEAD + d0 + x];
    __syncthreads();
    #pragma unroll
    for (int i = 0; i < 4; i++) {
        float v = t[x][y + i * 8];
        size_t o = (size_t)(bh * DHEAD + d0 + y + i * 8) * SEQ + s0 + x;
        Vh[o] = __float2bfloat16(v);
        Vl[o] = __float2bfloat16(bfres(v));
    }
}

// ---------------------------------------------------------------------------
// bf16 3-term split GEMM via mma.sync (smooth paths: Q, O projections)
// ---------------------------------------------------------------------------
#define MM_STRIDE 80
#define MM_TILE  (128 * MM_STRIDE)
#define MM_BUF   (4 * MM_TILE)
#define MM_SMEM  (2 * MM_BUF)              // 81920 B

__global__ __launch_bounds__(256) void gemm_mma_kernel(
    const __nv_bfloat16* __restrict__ A0, const __nv_bfloat16* __restrict__ A1,
    const __nv_bfloat16* __restrict__ B0, const __nv_bfloat16* __restrict__ B1,
    float* __restrict__ C)
{
    extern __shared__ char sm[];
    const uint32_t sbase = smem_u32(sm);
    const int tid = threadIdx.x;
    const int lane = tid & 31;
    const int wid = tid >> 5;
    const int wm = wid >> 2;
    const int wn = wid & 3;
    const int mrow0 = blockIdx.y * 128;
    const int ncol0 = blockIdx.x * 128;

    const int a_row_l = lane & 15;
    const int a_col_l = (lane >> 4) * 8;
    const int b_n_l   = (lane & 7) | ((lane & 16) >> 1);
    const int b_k_l   = (lane & 8);

    float acc[4][4][4];
    #pragma unroll
    for (int i = 0; i < 4; i++)
        #pragma unroll
        for (int j = 0; j < 4; j++)
            #pragma unroll
            for (int e = 0; e < 4; e++) acc[i][j][e] = 0.f;

    const __nv_bfloat16* srcs[4] = { A0, A1, B0, B1 };

    const int row0 = tid >> 2,  sc0 = tid & 3;
    const int row1 = (tid + 256) >> 2, sc1 = (tid + 256) & 3;

    auto issue = [&](int c, int buf) {
        const int k0 = c * 32;
        #pragma unroll
        for (int t = 0; t < 4; t++) {
            const __nv_bfloat16* src = srcs[t];
            const int rbase = (t < 2) ? mrow0 : ncol0;
            uint32_t sb = sbase + buf * MM_BUF + t * MM_TILE;
            cp16(sb + row0 * MM_STRIDE + sc0 * 16,
                 src + (size_t)(rbase + row0) * DM + k0 + sc0 * 8);
            cp16(sb + row1 * MM_STRIDE + sc1 * 16,
                 src + (size_t)(rbase + row1) * DM + k0 + sc1 * 8);
        }
    };

    issue(0, 0);
    cp_commit();

    const int a_r0 = wm * 64;
    const int b_n0 = wn * 32;

    for (int c = 0; c < DM / 32; c++) {
        const int buf = c & 1;
        if (c + 1 < DM / 32) {
            issue(c + 1, buf ^ 1);
            cp_commit();
            cp_wait<1>();
        } else {
            cp_wait<0>();
        }
        __syncthreads();

        const uint32_t tA0 = sbase + buf * MM_BUF;
        const uint32_t tA1 = tA0 + MM_TILE;
        const uint32_t tB0 = tA0 + 2 * MM_TILE;
        const uint32_t tB1 = tA0 + 3 * MM_TILE;

        #pragma unroll
        for (int ks = 0; ks < 32; ks += 16) {
            const uint32_t aoff = (uint32_t)(a_r0 + a_row_l) * MM_STRIDE + (ks + a_col_l) * 2;
            const uint32_t boffA = (uint32_t)(b_n0 + b_n_l) * MM_STRIDE + (ks + b_k_l) * 2;
            const uint32_t boffB = (uint32_t)(b_n0 + 16 + b_n_l) * MM_STRIDE + (ks + b_k_l) * 2;

            uint32_t a0f[4][4], a1f[4][4], b0f[2][4], b1f[2][4];

            ldsm4(b0f[0], tB0 + boffA);
            ldsm4(b0f[1], tB0 + boffB);
            #pragma unroll
            for (int ma = 0; ma < 4; ma++)
                ldsm4(a0f[ma], tA0 + aoff + ma * 16 * MM_STRIDE);
            #pragma unroll
            for (int ma = 0; ma < 4; ma++)
                #pragma unroll
                for (int na = 0; na < 4; na++)
                    mma16816(acc[ma][na], a0f[ma], &b0f[na >> 1][(na & 1) * 2]);

            ldsm4(b1f[0], tB1 + boffA);
            ldsm4(b1f[1], tB1 + boffB);
            #pragma unroll
            for (int ma = 0; ma < 4; ma++)
                #pragma unroll
                for (int na = 0; na < 4; na++)
                    mma16816(acc[ma][na], a0f[ma], &b1f[na >> 1][(na & 1) * 2]);

            #pragma unroll
            for (int ma = 0; ma < 4; ma++)
                ldsm4(a1f[ma], tA1 + aoff + ma * 16 * MM_STRIDE);
            #pragma unroll
            for (int ma = 0; ma < 4; ma++)
                #pragma unroll
                for (int na = 0; na < 4; na++)
                    mma16816(acc[ma][na], a1f[ma], &b0f[na >> 1][(na & 1) * 2]);
        }
        __syncthreads();
    }

    #pragma unroll
    for (int ma = 0; ma < 4; ma++) {
        #pragma unroll
        for (int na = 0; na < 4; na++) {
            const int r = mrow0 + wm * 64 + ma * 16 + (lane >> 2);
            const int cc = ncol0 + wn * 32 + na * 8 + (lane & 3) * 2;
            *(float2*)&C[(size_t)r * DM + cc] = make_float2(acc[ma][na][0], acc[ma][na][1]);
            *(float2*)&C[(size_t)(r + 8) * DM + cc] = make_float2(acc[ma][na][2], acc[ma][na][3]);
        }
    }
}

// ---------------------------------------------------------------------------
// RMSNorm in-place (Q path only now)
// ---------------------------------------------------------------------------
__global__ __launch_bounds__(256) void rmsnorm_kernel(
    float* __restrict__ y, const float* __restrict__ w)
{
    __shared__ float red[256];
    const int t = threadIdx.x;
    float* p = y + (size_t)blockIdx.x * DM;

    float ss = 0.f;
    for (int i = t; i < DM; i += 256) { float v = p[i]; ss += v * v; }
    red[t] = ss;
    __syncthreads();
    for (int o = 128; o > 0; o >>= 1) {
        if (t < o) red[t] += red[t + o];
        __syncthreads();
    }
    const float r = rsqrtf(red[0] / (float)DM + 1e-6f);
    for (int i = t; i < DM; i += 256) p[i] = p[i] * r * w[i];
}

// ---------------------------------------------------------------------------
// Fused K-tail: rmsnorm + RotorQuant + bf16 hi/lo split, one token per block.
// Reduction trees and expression order EXACTLY match the separate kernels.
// ---------------------------------------------------------------------------
__global__ __launch_bounds__(256) void kpost_kernel(
    const float* __restrict__ Kin, const float* __restrict__ w,
    const float* __restrict__ Mg, const float* __restrict__ Mtg,
    const float* __restrict__ Cg,
    __nv_bfloat16* __restrict__ Kh, __nv_bfloat16* __restrict__ Kl)
{
    __shared__ float row[DM];
    __shared__ float red[256];
    __shared__ float gred[4][64];
    __shared__ float xs[4][66];
    __shared__ float ys[4][66];
    __shared__ float Cs[8];
    __shared__ float Ms[NGROUPS * 9];
    __shared__ float Mts[NGROUPS * 9];

    const int t = threadIdx.x;
    const float* p = Kin + (size_t)blockIdx.x * DM;

    float ss = 0.f;
    for (int i = t; i < DM; i += 256) { float v = p[i]; row[i] = v; ss += v * v; }
    red[t] = ss;
    if (t < NGROUPS * 9) { Ms[t] = Mg[t]; Mts[t] = Mtg[t]; }
    if (t < 8) Cs[t] = Cg[t];
    __syncthreads();
    for (int o = 128; o > 0; o >>= 1) {
        if (t < o) red[t] += red[t + o];
        __syncthreads();
    }
    const float r = rsqrtf(red[0] / (float)DM + 1e-6f);
    for (int i = t; i < DM; i += 256) row[i] = row[i] * r * w[i];
    __syncthreads();

    const int g = t >> 6;       // head group 0..3
    const int lt = t & 63;

    for (int hb = 0; hb < 8; hb++) {
        const int h = hb * 4 + g;
        const float v = row[h * DHEAD + lt];
        gred[g][lt] = v * v;
        __syncthreads();
        for (int o = 32; o > 0; o >>= 1) {
            if (lt < o) gred[g][lt] += gred[g][lt + o];
            __syncthreads();
        }
        const float norm = fmaxf(sqrtf(gred[g][0]), 1e-8f);
        xs[g][lt] = v / norm;
        if (lt < 2) xs[g][64 + lt] = 0.f;
        __syncthreads();

        if (lt < NGROUPS) {
            const float g0 = xs[g][3 * lt + 0];
            const float g1 = xs[g][3 * lt + 1];
            const float g2 = xs[g][3 * lt + 2];
            const float* m = Ms + lt * 9;
            float r0 = g0 * m[0] + g1 * m[3] + g2 * m[6];
            float r1 = g0 * m[1] + g1 * m[4] + g2 * m[7];
            float r2 = g0 * m[2] + g1 * m[5] + g2 * m[8];

            const float C0 = Cs[0];
            const float invstep = 1.f / (Cs[1] - Cs[0]);
            float q[3];
            float rr[3] = { r0, r1, r2 };
            #pragma unroll
            for (int e = 0; e < 3; e++) {
                int i = (int)floorf((rr[e] - C0) * invstep);
                i = max(0, min(6, i));
                float d0 = fabsf(rr[e] - Cs[i]);
                float d1 = fabsf(rr[e] - Cs[i + 1]);
                q[e] = (d0 <= d1) ? Cs[i] : Cs[i + 1];
            }

            const float* mt2 = Mts + lt * 9;
            ys[g][3 * lt + 0] = q[0] * mt2[0] + q[1] * mt2[3] + q[2] * mt2[6];
            ys[g][3 * lt + 1] = q[0] * mt2[1] + q[1] * mt2[4] + q[2] * mt2[7];
            ys[g][3 * lt + 2] = q[0] * mt2[2] + q[1] * mt2[5] + q[2] * mt2[8];
        }
        __syncthreads();

        const float outv = ys[g][lt] * norm;
        const size_t o = (size_t)blockIdx.x * DM + h * DHEAD + lt;
        __nv_bfloat16 hh = __float2bfloat16(outv);
        Kh[o] = hh;
        Kl[o] = __float2bfloat16(outv - __bfloat162float(hh));
        __syncthreads();
    }
}

// ---------------------------------------------------------------------------
// RotorQuant roundtrip in-place (V path). Unchanged.
// ---------------------------------------------------------------------------
__global__ __launch_bounds__(64) void quant_kernel(
    float* __restrict__ data,
    const float* __restrict__ Mg, const float* __restrict__ Mtg,
    const float* __restrict__ Cg)
{
    __shared__ float xs[66];
    __shared__ float ys[66];
    __shared__ float red[64];
    __shared__ float Cs[8];
    __shared__ float Ms[NGROUPS * 9];
    __shared__ float Mts[NGROUPS * 9];

    const int t = threadIdx.x;
    const int idx = blockIdx.x;
    const int s = idx & (SEQ - 1);
    const int h = (idx >> 10) & (HEADS - 1);
    const int b = idx >> 15;

    float* p = data + ((size_t)(b * SEQ + s)) * DM + h * DHEAD;

    for (int i = t; i < NGROUPS * 9; i += 64) { Ms[i] = Mg[i]; Mts[i] = Mtg[i]; }
    if (t < 8) Cs[t] = Cg[t];

    const float v = p[t];
    red[t] = v * v;
    __syncthreads();
    for (int o = 32; o > 0; o >>= 1) {
        if (t < o) red[t] += red[t + o];
        __syncthreads();
    }
    const float norm = fmaxf(sqrtf(red[0]), 1e-8f);
    xs[t] = v / norm;
    if (t < 2) xs[64 + t] = 0.f;
    __syncthreads();

    if (t < NGROUPS) {
        const float g0 = xs[3 * t + 0];
        const float g1 = xs[3 * t + 1];
        const float g2 = xs[3 * t + 2];
        const float* m = Ms + t * 9;
        float r0 = g0 * m[0] + g1 * m[3] + g2 * m[6];
        float r1 = g0 * m[1] + g1 * m[4] + g2 * m[7];
        float r2 = g0 * m[2] + g1 * m[5] + g2 * m[8];

        const float C0 = Cs[0];
        const float invstep = 1.f / (Cs[1] - Cs[0]);
        float q[3];
        float rr[3] = { r0, r1, r2 };
        #pragma unroll
        for (int e = 0; e < 3; e++) {
            int i = (int)floorf((rr[e] - C0) * invstep);
            i = max(0, min(6, i));
            float d0 = fabsf(rr[e] - Cs[i]);
            float d1 = fabsf(rr[e] - Cs[i + 1]);
            q[e] = (d0 <= d1) ? Cs[i] : Cs[i + 1];
        }

        const float* mt2 = Mts + t * 9;
        ys[3 * t + 0] = q[0] * mt2[0] + q[1] * mt2[3] + q[2] * mt2[6];
        ys[3 * t + 1] = q[0] * mt2[1] + q[1] * mt2[4] + q[2] * mt2[7];
        ys[3 * t + 2] = q[0] * mt2[2] + q[1] * mt2[5] + q[2] * mt2[8];
    }
    __syncthreads();
    p[t] = ys[t] * norm;
}

// ---------------------------------------------------------------------------
// Tensor-core flash attention: 128 queries/CTA (8 warps), 64-key chunks,
// K/V bf16 hi/lo pre-converted; cp.async double-buffered.
// Writes output directly as bf16 hi/lo (fused O-split).
// ---------------------------------------------------------------------------
#define AT_STRIDE_B 144
#define AT_TILE64 (64 * AT_STRIDE_B)            // 9216 B
#define AT_QTILE  (128 * AT_STRIDE_B)           // 18432 B
#define AT_SMEM   (2 * AT_QTILE + 8 * AT_TILE64)  // 110592 B

__global__ __launch_bounds__(256) void attn_mma_kernel(
    const float* __restrict__ Q,
    const __nv_bfloat16* __restrict__ Kbh, const __nv_bfloat16* __restrict__ Kbl,
    const __nv_bfloat16* __restrict__ Vth, const __nv_bfloat16* __restrict__ Vtl,
    __nv_bfloat16* __restrict__ Oh, __nv_bfloat16* __restrict__ Ol)
{
    extern __shared__ char smat[];
    const uint32_t sb = smem_u32(smat);
    const uint32_t QhB = sb;
    const uint32_t QlB = sb + AT_QTILE;

    const int tid = threadIdx.x;
    const int lane = tid & 31;
    const int w = tid >> 5;          // 0..7
    const int qt = blockIdx.x;       // 0..7 (128-query tiles)
    const int h = blockIdx.y;
    const int b = blockIdx.z;
    const int bh = b * HEADS + h;

    const int a_row_l = lane & 15;
    const int a_col_l = (lane >> 4) * 8;
    const int b_n_l   = (lane & 7) | ((lane & 16) >> 1);
    const int b_k_l   = (lane & 8);

    // ---- convert Q tile (scaled by 1/8) to bf16 hi/lo ----
    {
        const int cr = tid >> 1;            // 0..127
        const int cd = (tid & 1) * 32;
        const float* qrow = Q + ((size_t)(b * SEQ + qt * 128 + cr)) * DM + h * DHEAD + cd;
        #pragma unroll
        for (int s = 0; s < 8; s++) {
            float4 v = *(const float4*)(qrow + s * 4);
            float f[4] = { v.x * 0.125f, v.y * 0.125f, v.z * 0.125f, v.w * 0.125f };
            uint32_t off = (uint32_t)cr * AT_STRIDE_B + (cd + s * 4) * 2;
            *(uint32_t*)(smat + off)                = pack2bf(f[0], f[1]);
            *(uint32_t*)(smat + off + 4)            = pack2bf(f[2], f[3]);
            *(uint32_t*)(smat + AT_QTILE + off)     = pack2bf(bfres(f[0]), bfres(f[1]));
            *(uint32_t*)(smat + AT_QTILE + off + 4) = pack2bf(bfres(f[2]), bfres(f[3]));
        }
    }

    auto prefetch = [&](int kt, int buf) {
        const uint32_t base = sb + 2 * AT_QTILE + buf * 4 * AT_TILE64;
        const __nv_bfloat16* kh = Kbh + ((size_t)(b * SEQ + kt * 64)) * DM + h * DHEAD;
        const __nv_bfloat16* kl = Kbl + ((size_t)(b * SEQ + kt * 64)) * DM + h * DHEAD;
        const __nv_bfloat16* vh = Vth + (size_t)bh * DHEAD * SEQ + kt * 64;
        const __nv_bfloat16* vl = Vtl + (size_t)bh * DHEAD * SEQ + kt * 64;
        #pragma unroll
        for (int i = 0; i < 2; i++) {
            const int idx = tid + i * 256;
            const int r = idx >> 3, sg = idx & 7;
            const uint32_t dst = base + (uint32_t)r * AT_STRIDE_B + sg * 16;
            cp16(dst,                 kh + (size_t)r * DM + sg * 8);
            cp16(dst + AT_TILE64,     kl + (size_t)r * DM + sg * 8);
            cp16(dst + 2 * AT_TILE64, vh + (size_t)r * SEQ + sg * 8);
            cp16(dst + 3 * AT_TILE64, vl + (size_t)r * SEQ + sg * 8);
        }
    };

    float S[8][4], Of[8][4];
    #pragma unroll
    for (int a = 0; a < 8; a++)
        #pragma unroll
        for (int e = 0; e < 4; e++) Of[a][e] = 0.f;
    float m0 = -1e30f, m1 = -1e30f, l0 = 0.f, l1 = 0.f;

    prefetch(0, 0);
    cp_commit();

    for (int kt = 0; kt < SEQ / 64; kt++) {
        const int buf = kt & 1;
        __syncthreads();
        if (kt + 1 < SEQ / 64) {
            prefetch(kt + 1, buf ^ 1);
            cp_commit();
            cp_wait<1>();
        } else {
            cp_wait<0>();
        }
        __syncthreads();

        const uint32_t KhB = sb + 2 * AT_QTILE + buf * 4 * AT_TILE64;
        const uint32_t KlB = KhB + AT_TILE64;
        const uint32_t VhB = KhB + 2 * AT_TILE64;
        const uint32_t VlB = KhB + 3 * AT_TILE64;

        #pragma unroll
        for (int a = 0; a < 8; a++)
            #pragma unroll
            for (int e = 0; e < 4; e++) S[a][e] = 0.f;

        #pragma unroll
        for (int kd = 0; kd < 4; kd++) {
            uint32_t qh[4], ql[4], kh[4][4], kl[4][4];
            const uint32_t qoff = (uint32_t)(w * 16 + a_row_l) * AT_STRIDE_B + (kd * 16 + a_col_l) * 2;
            ldsm4(qh, QhB + qoff);
            ldsm4(ql, QlB + qoff);
            #pragma unroll
            for (int g = 0; g < 4; g++) {
                const uint32_t koff = (uint32_t)(g * 16 + b_n_l) * AT_STRIDE_B + (kd * 16 + b_k_l) * 2;
                ldsm4(kh[g], KhB + koff);
                ldsm4(kl[g], KlB + koff);
            }
            #pragma unroll
            for (int g = 0; g < 4; g++) {
                mma16816(S[2*g],   qh, &kh[g][0]);
                mma16816(S[2*g+1], qh, &kh[g][2]);
                mma16816(S[2*g],   ql, &kh[g][0]);
                mma16816(S[2*g+1], ql, &kh[g][2]);
                mma16816(S[2*g],   qh, &kl[g][0]);
                mma16816(S[2*g+1], qh, &kl[g][2]);
            }
        }

        float mx0 = -1e30f, mx1 = -1e30f;
        #pragma unroll
        for (int a = 0; a < 8; a++) {
            mx0 = fmaxf(mx0, fmaxf(S[a][0], S[a][1]));
            mx1 = fmaxf(mx1, fmaxf(S[a][2], S[a][3]));
        }
        mx0 = fmaxf(mx0, __shfl_xor_sync(0xffffffffu, mx0, 1));
        mx0 = fmaxf(mx0, __shfl_xor_sync(0xffffffffu, mx0, 2));
        mx1 = fmaxf(mx1, __shfl_xor_sync(0xffffffffu, mx1, 1));
        mx1 = fmaxf(mx1, __shfl_xor_sync(0xffffffffu, mx1, 2));
        const float mn0 = fmaxf(m0, mx0);
        const float mn1 = fmaxf(m1, mx1);
        const float corr0 = __expf(m0 - mn0);
        const float corr1 = __expf(m1 - mn1);
        m0 = mn0; m1 = mn1;
        l0 *= corr0; l1 *= corr1;
        #pragma unroll
        for (int a = 0; a < 8; a++) {
            Of[a][0] *= corr0; Of[a][1] *= corr0;
            Of[a][2] *= corr1; Of[a][3] *= corr1;
        }
        float ps0 = 0.f, ps1 = 0.f;
        #pragma unroll
        for (int a = 0; a < 8; a++) {
            S[a][0] = __expf(S[a][0] - m0);
            S[a][1] = __expf(S[a][1] - m0);
            S[a][2] = __expf(S[a][2] - m1);
            S[a][3] = __expf(S[a][3] - m1);
            ps0 += S[a][0] + S[a][1];
            ps1 += S[a][2] + S[a][3];
        }
        l0 += ps0; l1 += ps1;

        uint32_t pa[4][4], pl[4][4];
        #pragma unroll
        for (int kk = 0; kk < 4; kk++) {
            const int a0 = 2 * kk, a1 = 2 * kk + 1;
            pa[kk][0] = pack2bf(S[a0][0], S[a0][1]);
            pa[kk][1] = pack2bf(S[a0][2], S[a0][3]);
            pa[kk][2] = pack2bf(S[a1][0], S[a1][1]);
            pa[kk][3] = pack2bf(S[a1][2], S[a1][3]);
            pl[kk][0] = pack2bf(bfres(S[a0][0]), bfres(S[a0][1]));
            pl[kk][1] = pack2bf(bfres(S[a0][2]), bfres(S[a0][3]));
            pl[kk][2] = pack2bf(bfres(S[a1][0]), bfres(S[a1][1]));
            pl[kk][3] = pack2bf(bfres(S[a1][2]), bfres(S[a1][3]));
        }

        #pragma unroll
        for (int kk = 0; kk < 4; kk++) {
            uint32_t vh[4][4], vl[4][4];
            #pragma unroll
            for (int g = 0; g < 4; g++) {
                const uint32_t voff = (uint32_t)(g * 16 + b_n_l) * AT_STRIDE_B + (kk * 16 + b_k_l) * 2;
                ldsm4(vh[g], VhB + voff);
                ldsm4(vl[g], VlB + voff);
            }
            #pragma unroll
            for (int g = 0; g < 4; g++) {
                mma16816(Of[2*g],   pa[kk], &vh[g][0]);
                mma16816(Of[2*g+1], pa[kk], &vh[g][2]);
                mma16816(Of[2*g],   pl[kk], &vh[g][0]);
                mma16816(Of[2*g+1], pl[kk], &vh[g][2]);
                mma16816(Of[2*g],   pa[kk], &vl[g][0]);
                mma16816(Of[2*g+1], pa[kk], &vl[g][2]);
            }
        }
    }

    l0 += __shfl_xor_sync(0xffffffffu, l0, 1);
    l0 += __shfl_xor_sync(0xffffffffu, l0, 2);
    l1 += __shfl_xor_sync(0xffffffffu, l1, 1);
    l1 += __shfl_xor_sync(0xffffffffu, l1, 2);
    const float inv0 = 1.f / l0;
    const float inv1 = 1.f / l1;

    const int r0 = qt * 128 + w * 16 + (lane >> 2);
    const int r1 = r0 + 8;
    #pragma unroll
    for (int a = 0; a < 8; a++) {
        const int d = h * DHEAD + a * 8 + (lane & 3) * 2;
        const size_t o0 = ((size_t)(b * SEQ + r0)) * DM + d;
        const size_t o1 = ((size_t)(b * SEQ + r1)) * DM + d;
        float f00 = Of[a][0] * inv0, f01 = Of[a][1] * inv0;
        float f10 = Of[a][2] * inv1, f11 = Of[a][3] * inv1;
        *(uint32_t*)&Oh[o0] = pack2bf(f00, f01);
        *(uint32_t*)&Ol[o0] = pack2bf(bfres(f00), bfres(f01));
        *(uint32_t*)&Oh[o1] = pack2bf(f10, f11);
        *(uint32_t*)&Ol[o1] = pack2bf(bfres(f10), bfres(f11));
    }
}

// ---------------------------------------------------------------------------
// Launch
// ---------------------------------------------------------------------------
extern "C" void kernel_launch(void* const* d_in, const int* in_sizes, int n_in,
                              void* d_out, int out_size)
{
    const float* x    = (const float*)d_in[0];
    const float* Wq   = (const float*)d_in[1];
    const float* Wk   = (const float*)d_in[2];
    const float* Wv   = (const float*)d_in[3];
    const float* Wo   = (const float*)d_in[4];
    const float* qn_w = (const float*)d_in[5];
    const float* kn_w = (const float*)d_in[6];
    const float* Mk   = (const float*)d_in[7];
    const float* Mtk  = (const float*)d_in[8];
    const float* Ck   = (const float*)d_in[9];
    const float* Mv   = (const float*)d_in[10];
    const float* Mtv  = (const float*)d_in[11];
    const float* Cv   = (const float*)d_in[12];
    float* out = (float*)d_out;

    float *pQ, *pK, *pV;
    cudaGetSymbolAddress((void**)&pQ, g_Q);
    cudaGetSymbolAddress((void**)&pK, g_K);
    cudaGetSymbolAddress((void**)&pV, g_V);

    __nv_bfloat16 *xh, *xl, *oh, *ol, *wqh, *wql, *woh, *wol;
    __nv_bfloat16 *kbh, *kbl, *vth, *vtl;
    cudaGetSymbolAddress((void**)&xh, g_xh);
    cudaGetSymbolAddress((void**)&xl, g_xl);
    cudaGetSymbolAddress((void**)&oh, g_oh);
    cudaGetSymbolAddress((void**)&ol, g_ol);
    cudaGetSymbolAddress((void**)&wqh, g_wqh);
    cudaGetSymbolAddress((void**)&wql, g_wql);
    cudaGetSymbolAddress((void**)&woh, g_woh);
    cudaGetSymbolAddress((void**)&wol, g_wol);
    cudaGetSymbolAddress((void**)&kbh, g_kbh);
    cudaGetSymbolAddress((void**)&kbl, g_kbl);
    cudaGetSymbolAddress((void**)&vth, g_vth);
    cudaGetSymbolAddress((void**)&vtl, g_vtl);

    static bool inited = false;
    static cudaStream_t sk = 0, sv = 0;
    static cudaEvent_t evRoot = 0, evK = 0, evV = 0;
    if (!inited) {
        cudaStreamCreateWithFlags(&sk, cudaStreamNonBlocking);
        cudaStreamCreateWithFlags(&sv, cudaStreamNonBlocking);
        cudaEventCreateWithFlags(&evRoot, cudaEventDisableTiming);
        cudaEventCreateWithFlags(&evK, cudaEventDisableTiming);
        cudaEventCreateWithFlags(&evV, cudaEventDisableTiming);
        cudaFuncSetAttribute(sgemm_nn,
                             cudaFuncAttributeMaxDynamicSharedMemorySize, SG_SMEM);
        cudaFuncSetAttribute(gemm_mma_kernel,
                             cudaFuncAttributeMaxDynamicSharedMemorySize, MM_SMEM);
        cudaFuncSetAttribute(attn_mma_kernel,
                             cudaFuncAttributeMaxDynamicSharedMemorySize, AT_SMEM);
        inited = true;
    }

    const int splitBlocks = (int)(NELEM / (256 * 4));
    dim3 tgrid(DM / 32, DM / 32);
    dim3 tblock(32, 8);
    dim3 fgrid(DM / BN, MTOK / BM);
    dim3 mgrid(DM / 128, MTOK / 128);
    dim3 vtgrid(SEQ / 32, DHEAD / 32, BATCH * HEADS);

    // fork
    cudaEventRecord(evRoot, 0);
    cudaStreamWaitEvent(sk, evRoot, 0);
    cudaStreamWaitEvent(sv, evRoot, 0);

    // K chain: fp32 GEMM -> fused rmsnorm+quant+split
    sgemm_nn<<<fgrid, 256, SG_SMEM, sk>>>(x, Wk, pK, MTOK, DM, DM);
    kpost_kernel<<<MTOK, 256, 0, sk>>>(pK, kn_w, Mk, Mtk, Ck, kbh, kbl);
    cudaEventRecord(evK, sk);

    // V chain: fp32 GEMM -> quant -> transpose+split
    sgemm_nn<<<fgrid, 256, SG_SMEM, sv>>>(x, Wv, pV, MTOK, DM, DM);
    quant_kernel<<<BATCH * HEADS * SEQ, 64, 0, sv>>>(pV, Mv, Mtv, Cv);
    convert_vt_kernel<<<vtgrid, tblock, 0, sv>>>(pV, vth, vtl);
    cudaEventRecord(evV, sv);

    // Q pipeline on main stream (overlaps with K/V sgemms)
    split_kernel<<<splitBlocks, 256>>>(x, xh, xl);
    tsplit_kernel<<<tgrid, tblock>>>(Wq, wqh, wql);
    tsplit_kernel<<<tgrid, tblock>>>(Wo, woh, wol);
    gemm_mma_kernel<<<mgrid, 256, MM_SMEM>>>(xh, xl, wqh, wql, pQ);
    rmsnorm_kernel<<<MTOK, 256>>>(pQ, qn_w);

    // join
    cudaStreamWaitEvent((cudaStream_t)0, evK, 0);
    cudaStreamWaitEvent((cudaStream_t)0, evV, 0);

    // attention: 128-query CTAs; writes bf16 hi/lo output directly
    attn_mma_kernel<<<dim3(SEQ / 128, HEADS, BATCH), 256, AT_SMEM>>>(
        pQ, kbh, kbl, vth, vtl, oh, ol);

    // O projection
    gemm_mma_kernel<<<mgrid, 256, MM_SMEM>>>(oh, ol, woh, wol, out);
}

// round 10
// speedup vs baseline: 1.0041x; 1.0041x over previous
#include <cuda_runtime.h>
#include <cuda_bf16.h>
#include <math.h>
#include <stdint.h>

#define BATCH 2
#define SEQ 1024
#define HEADS 32
#define DHEAD 64
#define DM 2048
#define MTOK (BATCH * SEQ)      // 2048
#define NGROUPS 22
#define NELEM ((size_t)DM * DM) // 4194304

// ---------------- scratch (device globals; no allocation allowed) ----------
__device__ float g_Q[(size_t)MTOK * DM];
__device__ float g_K[(size_t)MTOK * DM];
__device__ float g_V[(size_t)MTOK * DM];

__device__ __nv_bfloat16 g_xh[NELEM], g_xl[NELEM];
__device__ __nv_bfloat16 g_oh[NELEM], g_ol[NELEM];      // attn output bf16 hi/lo
__device__ __nv_bfloat16 g_wqh[NELEM], g_wql[NELEM];
__device__ __nv_bfloat16 g_woh[NELEM], g_wol[NELEM];
__device__ __nv_bfloat16 g_kbh[NELEM], g_kbl[NELEM];    // K (post-quant) [b*S+s][h*64+d]
__device__ __nv_bfloat16 g_vth[NELEM], g_vtl[NELEM];    // V^T [(b*H+h)*64+d][s]

// ---------------- helpers ---------------------------------------------------
__device__ __forceinline__ uint32_t smem_u32(const void* p) {
    uint32_t a;
    asm("{ .reg .u64 t; cvta.to.shared.u64 t, %1; cvt.u32.u64 %0, t; }"
        : "=r"(a) : "l"(p));
    return a;
}
__device__ __forceinline__ void ldsm4(uint32_t* r, uint32_t addr) {
    asm volatile("ldmatrix.sync.aligned.m8n8.x4.shared.b16 {%0,%1,%2,%3}, [%4];"
                 : "=r"(r[0]), "=r"(r[1]), "=r"(r[2]), "=r"(r[3]) : "r"(addr));
}
__device__ __forceinline__ void mma16816(float* d, const uint32_t* a, const uint32_t* b) {
    asm volatile(
        "mma.sync.aligned.m16n8k16.row.col.f32.bf16.bf16.f32 "
        "{%0,%1,%2,%3}, {%4,%5,%6,%7}, {%8,%9}, {%0,%1,%2,%3};"
        : "+f"(d[0]), "+f"(d[1]), "+f"(d[2]), "+f"(d[3])
        : "r"(a[0]), "r"(a[1]), "r"(a[2]), "r"(a[3]), "r"(b[0]), "r"(b[1]));
}
__device__ __forceinline__ void cp16(uint32_t s, const void* g) {
    uint64_t ga = __cvta_generic_to_global(g);
    asm volatile("cp.async.cg.shared.global [%0], [%1], 16;" :: "r"(s), "l"(ga));
}
__device__ __forceinline__ void cp_commit() {
    asm volatile("cp.async.commit_group;" ::: "memory");
}
template <int N>
__device__ __forceinline__ void cp_wait() {
    asm volatile("cp.async.wait_group %0;" :: "n"(N) : "memory");
}
__device__ __forceinline__ uint32_t pack2bf(float x, float y) {
    __nv_bfloat162 t = __floats2bfloat162_rn(x, y);
    return *(uint32_t*)&t;
}
__device__ __forceinline__ float bfres(float x) {
    return x - __bfloat162float(__float2bfloat16(x));
}
__device__ __forceinline__ void fma_f32x2(uint64_t& d, uint64_t a, uint64_t b) {
    asm("fma.rn.f32x2 %0, %1, %2, %0;" : "+l"(d) : "l"(a), "l"(b));
}

// ---------------------------------------------------------------------------
// fp32 SGEMM (K,V; numerics-critical; bit-identical FFMA chain).
// Duplicated-A smem layout: LDS.64 loads the (a,a) pair directly.
// ---------------------------------------------------------------------------
#define BM 128
#define BN 128
#define TM 8
#define TN 8
#define S2_BK 16
#define SG_SMEM ((2 * S2_BK * 2 * BM + 2 * S2_BK * BN) * 4)   // 49152 B

__global__ __launch_bounds__(256, 2) void sgemm_nn(
    const float* __restrict__ A, const float* __restrict__ B,
    float* __restrict__ C, int M, int N, int K)
{
    extern __shared__ float smf[];
    float* As2 = smf;                         // [2][S2_BK][256] duplicated
    float* BsD = smf + 2 * S2_BK * 2 * BM;    // [2][S2_BK][128]

    const int tid = threadIdx.x;
    const int block_row = blockIdx.y * BM;
    const int block_col = blockIdx.x * BN;

    const int am = tid >> 1;
    const int ak = (tid & 1) * 8;
    const int bk0 = tid >> 5;
    const int bn0 = (tid & 31) * 4;
    const int tr = (tid >> 4) * TM;
    const int tc = (tid & 15) * TN;

    const uint32_t bs_base = smem_u32(BsD);

    uint64_t acc2[TM][TN / 2];
    #pragma unroll
    for (int i = 0; i < TM; i++)
        #pragma unroll
        for (int j = 0; j < TN / 2; j++) acc2[i][j] = 0ull;

    float a0[8];
    auto ldgA = [&](int c) {
        float4 u = *(const float4*)&A[(size_t)(block_row + am) * K + c * S2_BK + ak];
        float4 v = *(const float4*)&A[(size_t)(block_row + am) * K + c * S2_BK + ak + 4];
        a0[0] = u.x; a0[1] = u.y; a0[2] = u.z; a0[3] = u.w;
        a0[4] = v.x; a0[5] = v.y; a0[6] = v.z; a0[7] = v.w;
    };
    auto stsA = [&](int buf) {
        #pragma unroll
        for (int i = 0; i < 8; i++) {
            float* d = As2 + ((buf * S2_BK + ak + i) * 2 * BM) + 2 * am;
            d[0] = a0[i];
            d[1] = a0[i];
        }
    };
    auto cpB = [&](int c, int buf) {
        cp16(bs_base + (uint32_t)((buf * S2_BK + bk0) * BN + bn0) * 4,
             &B[(size_t)(c * S2_BK + bk0) * N + block_col + bn0]);
        cp16(bs_base + (uint32_t)((buf * S2_BK + bk0 + 8) * BN + bn0) * 4,
             &B[(size_t)(c * S2_BK + bk0 + 8) * N + block_col + bn0]);
    };

    const int NCH = K / S2_BK;
    ldgA(0);
    cpB(0, 0);
    cp_commit();
    stsA(0);

    for (int c = 0; c < NCH; c++) {
        const int buf = c & 1;
        if (c + 1 < NCH) {
            ldgA(c + 1);
            cpB(c + 1, buf ^ 1);
            cp_commit();
            cp_wait<1>();
        } else {
            cp_wait<0>();
        }
        __syncthreads();

        #pragma unroll
        for (int kk = 0; kk < S2_BK; kk++) {
            const float* arow = As2 + ((buf * S2_BK + kk) * 2 * BM);
            const float* brow = BsD + ((buf * S2_BK + kk) * BN);
            uint64_t a2[TM], b2[TN / 2];
            #pragma unroll
            for (int i = 0; i < TM; i++)
                a2[i] = *(const uint64_t*)&arow[2 * (tr + i)];
            #pragma unroll
            for (int j = 0; j < TN / 2; j++)
                b2[j] = *(const uint64_t*)&brow[tc + 2 * j];
            #pragma unroll
            for (int i = 0; i < TM; i++)
                #pragma unroll
                for (int j = 0; j < TN / 2; j++)
                    fma_f32x2(acc2[i][j], a2[i], b2[j]);
        }
        if (c + 1 < NCH) stsA(buf ^ 1);
        __syncthreads();
    }

    #pragma unroll
    for (int i = 0; i < TM; i++) {
        float cvals[TN];
        #pragma unroll
        for (int j = 0; j < TN / 2; j++) {
            float lo, hi;
            asm("mov.b64 {%0, %1}, %2;" : "=f"(lo), "=f"(hi) : "l"(acc2[i][j]));
            cvals[2 * j] = lo;
            cvals[2 * j + 1] = hi;
        }
        #pragma unroll
        for (int j = 0; j < TN; j += 4) {
            float4 cv = make_float4(cvals[j], cvals[j+1], cvals[j+2], cvals[j+3]);
            *(float4*)&C[(size_t)(block_row + tr + i) * N + block_col + tc + j] = cv;
        }
    }
}

// ---------------------------------------------------------------------------
// 2-level split and weight transpose-split (unchanged numerics)
// ---------------------------------------------------------------------------
__global__ __launch_bounds__(256) void split_kernel(
    const float* __restrict__ src, __nv_bfloat16* __restrict__ hi,
    __nv_bfloat16* __restrict__ lo)
{
    size_t i = ((size_t)blockIdx.x * 256 + threadIdx.x) * 4;
    float4 v = *(const float4*)(src + i);
    float vv[4] = { v.x, v.y, v.z, v.w };
    __nv_bfloat16 h[4], l[4];
    #pragma unroll
    for (int e = 0; e < 4; e++) {
        h[e] = __float2bfloat16(vv[e]);
        l[e] = __float2bfloat16(vv[e] - __bfloat162float(h[e]));
    }
    *(__nv_bfloat162*)(hi + i)     = { h[0], h[1] };
    *(__nv_bfloat162*)(hi + i + 2) = { h[2], h[3] };
    *(__nv_bfloat162*)(lo + i)     = { l[0], l[1] };
    *(__nv_bfloat162*)(lo + i + 2) = { l[2], l[3] };
}

__global__ __launch_bounds__(256) void tsplit_kernel(
    const float* __restrict__ W, __nv_bfloat16* __restrict__ Th,
    __nv_bfloat16* __restrict__ Tl)
{
    __shared__ float t[32][33];
    const int x = threadIdx.x;
    const int y = threadIdx.y;
    const int n0 = blockIdx.x * 32;
    const int k0 = blockIdx.y * 32;
    #pragma unroll
    for (int i = 0; i < 4; i++)
        t[y + i * 8][x] = W[(size_t)(k0 + y + i * 8) * DM + n0 + x];
    __syncthreads();
    #pragma unroll
    for (int i = 0; i < 4; i++) {
        float v = t[x][y + i * 8];
        __nv_bfloat16 h = __float2bfloat16(v);
        __nv_bfloat16 l = __float2bfloat16(v - __bfloat162float(h));
        size_t o = (size_t)(n0 + y + i * 8) * DM + k0 + x;
        Th[o] = h;
        Tl[o] = l;
    }
}

// Per-(b,h) transpose + split: V[(b*S+s)][h*64+d] -> Vt[(b*H+h)*64+d][s]
__global__ __launch_bounds__(256) void convert_vt_kernel(
    const float* __restrict__ V, __nv_bfloat16* __restrict__ Vh,
    __nv_bfloat16* __restrict__ Vl)
{
    __shared__ float t[32][33];
    const int x = threadIdx.x;
    const int y = threadIdx.y;
    const int s0 = blockIdx.x * 32;
    const int d0 = blockIdx.y * 32;
    const int bh = blockIdx.z;
    const int b = bh >> 5;
    const int h = bh & 31;
    #pragma unroll
    for (int i = 0; i < 4; i++)
        t[y + i * 8][x] = V[(size_t)(b * SEQ + s0 + y + i * 8) * DM + h * DHEAD + d0 + x];
    __syncthreads();
    #pragma unroll
    for (int i = 0; i < 4; i++) {
        float v = t[x][y + i * 8];
        size_t o = (size_t)(bh * DHEAD + d0 + y + i * 8) * SEQ + s0 + x;
        Vh[o] = __float2bfloat16(v);
        Vl[o] = __float2bfloat16(bfres(v));
    }
}

// ---------------------------------------------------------------------------
// bf16 3-term split GEMM via mma.sync (smooth paths: Q, O projections)
// ---------------------------------------------------------------------------
#define MM_STRIDE 80
#define MM_TILE  (128 * MM_STRIDE)
#define MM_BUF   (4 * MM_TILE)
#define MM_SMEM  (2 * MM_BUF)              // 81920 B

__global__ __launch_bounds__(256) void gemm_mma_kernel(
    const __nv_bfloat16* __restrict__ A0, const __nv_bfloat16* __restrict__ A1,
    const __nv_bfloat16* __restrict__ B0, const __nv_bfloat16* __restrict__ B1,
    float* __restrict__ C)
{
    extern __shared__ char sm[];
    const uint32_t sbase = smem_u32(sm);
    const int tid = threadIdx.x;
    const int lane = tid & 31;
    const int wid = tid >> 5;
    const int wm = wid >> 2;
    const int wn = wid & 3;
    const int mrow0 = blockIdx.y * 128;
    const int ncol0 = blockIdx.x * 128;

    const int a_row_l = lane & 15;
    const int a_col_l = (lane >> 4) * 8;
    const int b_n_l   = (lane & 7) | ((lane & 16) >> 1);
    const int b_k_l   = (lane & 8);

    float acc[4][4][4];
    #pragma unroll
    for (int i = 0; i < 4; i++)
        #pragma unroll
        for (int j = 0; j < 4; j++)
            #pragma unroll
            for (int e = 0; e < 4; e++) acc[i][j][e] = 0.f;

    const __nv_bfloat16* srcs[4] = { A0, A1, B0, B1 };

    const int row0 = tid >> 2,  sc0 = tid & 3;
    const int row1 = (tid + 256) >> 2, sc1 = (tid + 256) & 3;

    auto issue = [&](int c, int buf) {
        const int k0 = c * 32;
        #pragma unroll
        for (int t = 0; t < 4; t++) {
            const __nv_bfloat16* src = srcs[t];
            const int rbase = (t < 2) ? mrow0 : ncol0;
            uint32_t sb = sbase + buf * MM_BUF + t * MM_TILE;
            cp16(sb + row0 * MM_STRIDE + sc0 * 16,
                 src + (size_t)(rbase + row0) * DM + k0 + sc0 * 8);
            cp16(sb + row1 * MM_STRIDE + sc1 * 16,
                 src + (size_t)(rbase + row1) * DM + k0 + sc1 * 8);
        }
    };

    issue(0, 0);
    cp_commit();

    const int a_r0 = wm * 64;
    const int b_n0 = wn * 32;

    for (int c = 0; c < DM / 32; c++) {
        const int buf = c & 1;
        if (c + 1 < DM / 32) {
            issue(c + 1, buf ^ 1);
            cp_commit();
            cp_wait<1>();
        } else {
            cp_wait<0>();
        }
        __syncthreads();

        const uint32_t tA0 = sbase + buf * MM_BUF;
        const uint32_t tA1 = tA0 + MM_TILE;
        const uint32_t tB0 = tA0 + 2 * MM_TILE;
        const uint32_t tB1 = tA0 + 3 * MM_TILE;

        #pragma unroll
        for (int ks = 0; ks < 32; ks += 16) {
            const uint32_t aoff = (uint32_t)(a_r0 + a_row_l) * MM_STRIDE + (ks + a_col_l) * 2;
            const uint32_t boffA = (uint32_t)(b_n0 + b_n_l) * MM_STRIDE + (ks + b_k_l) * 2;
            const uint32_t boffB = (uint32_t)(b_n0 + 16 + b_n_l) * MM_STRIDE + (ks + b_k_l) * 2;

            uint32_t a0f[4][4], a1f[4][4], b0f[2][4], b1f[2][4];

            ldsm4(b0f[0], tB0 + boffA);
            ldsm4(b0f[1], tB0 + boffB);
            #pragma unroll
            for (int ma = 0; ma < 4; ma++)
                ldsm4(a0f[ma], tA0 + aoff + ma * 16 * MM_STRIDE);
            #pragma unroll
            for (int ma = 0; ma < 4; ma++)
                #pragma unroll
                for (int na = 0; na < 4; na++)
                    mma16816(acc[ma][na], a0f[ma], &b0f[na >> 1][(na & 1) * 2]);

            ldsm4(b1f[0], tB1 + boffA);
            ldsm4(b1f[1], tB1 + boffB);
            #pragma unroll
            for (int ma = 0; ma < 4; ma++)
                #pragma unroll
                for (int na = 0; na < 4; na++)
                    mma16816(acc[ma][na], a0f[ma], &b1f[na >> 1][(na & 1) * 2]);

            #pragma unroll
            for (int ma = 0; ma < 4; ma++)
                ldsm4(a1f[ma], tA1 + aoff + ma * 16 * MM_STRIDE);
            #pragma unroll
            for (int ma = 0; ma < 4; ma++)
                #pragma unroll
                for (int na = 0; na < 4; na++)
                    mma16816(acc[ma][na], a1f[ma], &b0f[na >> 1][(na & 1) * 2]);
        }
        __syncthreads();
    }

    #pragma unroll
    for (int ma = 0; ma < 4; ma++) {
        #pragma unroll
        for (int na = 0; na < 4; na++) {
            const int r = mrow0 + wm * 64 + ma * 16 + (lane >> 2);
            const int cc = ncol0 + wn * 32 + na * 8 + (lane & 3) * 2;
            *(float2*)&C[(size_t)r * DM + cc] = make_float2(acc[ma][na][0], acc[ma][na][1]);
            *(float2*)&C[(size_t)(r + 8) * DM + cc] = make_float2(acc[ma][na][2], acc[ma][na][3]);
        }
    }
}

// ---------------------------------------------------------------------------
// RMSNorm in-place (Q path)
// ---------------------------------------------------------------------------
__global__ __launch_bounds__(256) void rmsnorm_kernel(
    float* __restrict__ y, const float* __restrict__ w)
{
    __shared__ float red[256];
    const int t = threadIdx.x;
    float* p = y + (size_t)blockIdx.x * DM;

    float ss = 0.f;
    for (int i = t; i < DM; i += 256) { float v = p[i]; ss += v * v; }
    red[t] = ss;
    __syncthreads();
    for (int o = 128; o > 0; o >>= 1) {
        if (t < o) red[t] += red[t + o];
        __syncthreads();
    }
    const float r = rsqrtf(red[0] / (float)DM + 1e-6f);
    for (int i = t; i < DM; i += 256) p[i] = p[i] * r * w[i];
}

// ---------------------------------------------------------------------------
// Fused K-tail: rmsnorm + RotorQuant + bf16 hi/lo split (bit-identical).
// ---------------------------------------------------------------------------
__global__ __launch_bounds__(256) void kpost_kernel(
    const float* __restrict__ Kin, const float* __restrict__ w,
    const float* __restrict__ Mg, const float* __restrict__ Mtg,
    const float* __restrict__ Cg,
    __nv_bfloat16* __restrict__ Kh, __nv_bfloat16* __restrict__ Kl)
{
    __shared__ float row[DM];
    __shared__ float red[256];
    __shared__ float gred[4][64];
    __shared__ float xs[4][66];
    __shared__ float ys[4][66];
    __shared__ float Cs[8];
    __shared__ float Ms[NGROUPS * 9];
    __shared__ float Mts[NGROUPS * 9];

    const int t = threadIdx.x;
    const float* p = Kin + (size_t)blockIdx.x * DM;

    float ss = 0.f;
    for (int i = t; i < DM; i += 256) { float v = p[i]; row[i] = v; ss += v * v; }
    red[t] = ss;
    if (t < NGROUPS * 9) { Ms[t] = Mg[t]; Mts[t] = Mtg[t]; }
    if (t < 8) Cs[t] = Cg[t];
    __syncthreads();
    for (int o = 128; o > 0; o >>= 1) {
        if (t < o) red[t] += red[t + o];
        __syncthreads();
    }
    const float r = rsqrtf(red[0] / (float)DM + 1e-6f);
    for (int i = t; i < DM; i += 256) row[i] = row[i] * r * w[i];
    __syncthreads();

    const int g = t >> 6;
    const int lt = t & 63;

    for (int hb = 0; hb < 8; hb++) {
        const int h = hb * 4 + g;
        const float v = row[h * DHEAD + lt];
        gred[g][lt] = v * v;
        __syncthreads();
        for (int o = 32; o > 0; o >>= 1) {
            if (lt < o) gred[g][lt] += gred[g][lt + o];
            __syncthreads();
        }
        const float norm = fmaxf(sqrtf(gred[g][0]), 1e-8f);
        xs[g][lt] = v / norm;
        if (lt < 2) xs[g][64 + lt] = 0.f;
        __syncthreads();

        if (lt < NGROUPS) {
            const float g0 = xs[g][3 * lt + 0];
            const float g1 = xs[g][3 * lt + 1];
            const float g2 = xs[g][3 * lt + 2];
            const float* m = Ms + lt * 9;
            float r0 = g0 * m[0] + g1 * m[3] + g2 * m[6];
            float r1 = g0 * m[1] + g1 * m[4] + g2 * m[7];
            float r2 = g0 * m[2] + g1 * m[5] + g2 * m[8];

            const float C0 = Cs[0];
            const float invstep = 1.f / (Cs[1] - Cs[0]);
            float q[3];
            float rr[3] = { r0, r1, r2 };
            #pragma unroll
            for (int e = 0; e < 3; e++) {
                int i = (int)floorf((rr[e] - C0) * invstep);
                i = max(0, min(6, i));
                float d0 = fabsf(rr[e] - Cs[i]);
                float d1 = fabsf(rr[e] - Cs[i + 1]);
                q[e] = (d0 <= d1) ? Cs[i] : Cs[i + 1];
            }

            const float* mt2 = Mts + lt * 9;
            ys[g][3 * lt + 0] = q[0] * mt2[0] + q[1] * mt2[3] + q[2] * mt2[6];
            ys[g][3 * lt + 1] = q[0] * mt2[1] + q[1] * mt2[4] + q[2] * mt2[7];
            ys[g][3 * lt + 2] = q[0] * mt2[2] + q[1] * mt2[5] + q[2] * mt2[8];
        }
        __syncthreads();

        const float outv = ys[g][lt] * norm;
        const size_t o = (size_t)blockIdx.x * DM + h * DHEAD + lt;
        __nv_bfloat16 hh = __float2bfloat16(outv);
        Kh[o] = hh;
        Kl[o] = __float2bfloat16(outv - __bfloat162float(hh));
        __syncthreads();
    }
}

// ---------------------------------------------------------------------------
// RotorQuant roundtrip in-place (V path).
// ---------------------------------------------------------------------------
__global__ __launch_bounds__(64) void quant_kernel(
    float* __restrict__ data,
    const float* __restrict__ Mg, const float* __restrict__ Mtg,
    const float* __restrict__ Cg)
{
    __shared__ float xs[66];
    __shared__ float ys[66];
    __shared__ float red[64];
    __shared__ float Cs[8];
    __shared__ float Ms[NGROUPS * 9];
    __shared__ float Mts[NGROUPS * 9];

    const int t = threadIdx.x;
    const int idx = blockIdx.x;
    const int s = idx & (SEQ - 1);
    const int h = (idx >> 10) & (HEADS - 1);
    const int b = idx >> 15;

    float* p = data + ((size_t)(b * SEQ + s)) * DM + h * DHEAD;

    for (int i = t; i < NGROUPS * 9; i += 64) { Ms[i] = Mg[i]; Mts[i] = Mtg[i]; }
    if (t < 8) Cs[t] = Cg[t];

    const float v = p[t];
    red[t] = v * v;
    __syncthreads();
    for (int o = 32; o > 0; o >>= 1) {
        if (t < o) red[t] += red[t + o];
        __syncthreads();
    }
    const float norm = fmaxf(sqrtf(red[0]), 1e-8f);
    xs[t] = v / norm;
    if (t < 2) xs[64 + t] = 0.f;
    __syncthreads();

    if (t < NGROUPS) {
        const float g0 = xs[3 * t + 0];
        const float g1 = xs[3 * t + 1];
        const float g2 = xs[3 * t + 2];
        const float* m = Ms + t * 9;
        float r0 = g0 * m[0] + g1 * m[3] + g2 * m[6];
        float r1 = g0 * m[1] + g1 * m[4] + g2 * m[7];
        float r2 = g0 * m[2] + g1 * m[5] + g2 * m[8];

        const float C0 = Cs[0];
        const float invstep = 1.f / (Cs[1] - Cs[0]);
        float q[3];
        float rr[3] = { r0, r1, r2 };
        #pragma unroll
        for (int e = 0; e < 3; e++) {
            int i = (int)floorf((rr[e] - C0) * invstep);
            i = max(0, min(6, i));
            float d0 = fabsf(rr[e] - Cs[i]);
            float d1 = fabsf(rr[e] - Cs[i + 1]);
            q[e] = (d0 <= d1) ? Cs[i] : Cs[i + 1];
        }

        const float* mt2 = Mts + t * 9;
        ys[3 * t + 0] = q[0] * mt2[0] + q[1] * mt2[3] + q[2] * mt2[6];
        ys[3 * t + 1] = q[0] * mt2[1] + q[1] * mt2[4] + q[2] * mt2[7];
        ys[3 * t + 2] = q[0] * mt2[2] + q[1] * mt2[5] + q[2] * mt2[8];
    }
    __syncthreads();
    p[t] = ys[t] * norm;
}

// ---------------------------------------------------------------------------
// Tensor-core flash attention: 64 queries/CTA (4 warps, proven shape),
// K/V bf16 hi/lo pre-converted, cp.async double-buffered,
// fused bf16 hi/lo output epilogue.
// ---------------------------------------------------------------------------
#define AT_STRIDE_B 144
#define AT_TILE (64 * AT_STRIDE_B)          // 9216 B
#define AT_SMEM (10 * AT_TILE)              // 92160 B

__global__ __launch_bounds__(128) void attn_mma_kernel(
    const float* __restrict__ Q,
    const __nv_bfloat16* __restrict__ Kbh, const __nv_bfloat16* __restrict__ Kbl,
    const __nv_bfloat16* __restrict__ Vth, const __nv_bfloat16* __restrict__ Vtl,
    __nv_bfloat16* __restrict__ Oh, __nv_bfloat16* __restrict__ Ol)
{
    extern __shared__ char smat[];
    const uint32_t sb = smem_u32(smat);
    const uint32_t QhB = sb;
    const uint32_t QlB = sb + AT_TILE;

    const int tid = threadIdx.x;
    const int lane = tid & 31;
    const int w = tid >> 5;
    const int qt = blockIdx.x;
    const int h = blockIdx.y;
    const int b = blockIdx.z;
    const int bh = b * HEADS + h;

    const int a_row_l = lane & 15;
    const int a_col_l = (lane >> 4) * 8;
    const int b_n_l   = (lane & 7) | ((lane & 16) >> 1);
    const int b_k_l   = (lane & 8);

    // ---- convert Q tile (scaled by 1/8) to bf16 hi/lo (once) ----
    {
        const int cr = tid >> 1;
        const int cd = (tid & 1) * 32;
        const float* qrow = Q + ((size_t)(b * SEQ + qt * 64 + cr)) * DM + h * DHEAD + cd;
        #pragma unroll
        for (int s = 0; s < 8; s++) {
            float4 v = *(const float4*)(qrow + s * 4);
            float f[4] = { v.x * 0.125f, v.y * 0.125f, v.z * 0.125f, v.w * 0.125f };
            uint32_t off = (uint32_t)cr * AT_STRIDE_B + (cd + s * 4) * 2;
            *(uint32_t*)(smat + off)               = pack2bf(f[0], f[1]);
            *(uint32_t*)(smat + off + 4)           = pack2bf(f[2], f[3]);
            *(uint32_t*)(smat + AT_TILE + off)     = pack2bf(bfres(f[0]), bfres(f[1]));
            *(uint32_t*)(smat + AT_TILE + off + 4) = pack2bf(bfres(f[2]), bfres(f[3]));
        }
    }

    auto prefetch = [&](int kt, int buf) {
        const uint32_t base = sb + 2 * AT_TILE + buf * 4 * AT_TILE;
        const __nv_bfloat16* kh = Kbh + ((size_t)(b * SEQ + kt * 64)) * DM + h * DHEAD;
        const __nv_bfloat16* kl = Kbl + ((size_t)(b * SEQ + kt * 64)) * DM + h * DHEAD;
        const __nv_bfloat16* vh = Vth + (size_t)bh * DHEAD * SEQ + kt * 64;
        const __nv_bfloat16* vl = Vtl + (size_t)bh * DHEAD * SEQ + kt * 64;
        #pragma unroll
        for (int i = 0; i < 4; i++) {
            const int idx = tid + i * 128;
            const int r = idx >> 3, sg = idx & 7;
            const uint32_t dst = base + (uint32_t)r * AT_STRIDE_B + sg * 16;
            cp16(dst,               kh + (size_t)r * DM + sg * 8);
            cp16(dst + AT_TILE,     kl + (size_t)r * DM + sg * 8);
            cp16(dst + 2 * AT_TILE, vh + (size_t)r * SEQ + sg * 8);
            cp16(dst + 3 * AT_TILE, vl + (size_t)r * SEQ + sg * 8);
        }
    };

    float S[8][4], Of[8][4];
    #pragma unroll
    for (int a = 0; a < 8; a++)
        #pragma unroll
        for (int e = 0; e < 4; e++) Of[a][e] = 0.f;
    float m0 = -1e30f, m1 = -1e30f, l0 = 0.f, l1 = 0.f;

    prefetch(0, 0);
    cp_commit();

    for (int kt = 0; kt < SEQ / 64; kt++) {
        const int buf = kt & 1;
        __syncthreads();
        if (kt + 1 < SEQ / 64) {
            prefetch(kt + 1, buf ^ 1);
            cp_commit();
            cp_wait<1>();
        } else {
            cp_wait<0>();
        }
        __syncthreads();

        const uint32_t KhB = sb + 2 * AT_TILE + buf * 4 * AT_TILE;
        const uint32_t KlB = KhB + AT_TILE;
        const uint32_t VhB = KhB + 2 * AT_TILE;
        const uint32_t VlB = KhB + 3 * AT_TILE;

        #pragma unroll
        for (int a = 0; a < 8; a++)
            #pragma unroll
            for (int e = 0; e < 4; e++) S[a][e] = 0.f;

        #pragma unroll
        for (int kd = 0; kd < 4; kd++) {
            uint32_t qh[4], ql[4], kh[4][4], kl[4][4];
            const uint32_t qoff = (uint32_t)(w * 16 + a_row_l) * AT_STRIDE_B + (kd * 16 + a_col_l) * 2;
            ldsm4(qh, QhB + qoff);
            ldsm4(ql, QlB + qoff);
            #pragma unroll
            for (int g = 0; g < 4; g++) {
                const uint32_t koff = (uint32_t)(g * 16 + b_n_l) * AT_STRIDE_B + (kd * 16 + b_k_l) * 2;
                ldsm4(kh[g], KhB + koff);
                ldsm4(kl[g], KlB + koff);
            }
            #pragma unroll
            for (int g = 0; g < 4; g++) {
                mma16816(S[2*g],   qh, &kh[g][0]);
                mma16816(S[2*g+1], qh, &kh[g][2]);
                mma16816(S[2*g],   ql, &kh[g][0]);
                mma16816(S[2*g+1], ql, &kh[g][2]);
                mma16816(S[2*g],   qh, &kl[g][0]);
                mma16816(S[2*g+1], qh, &kl[g][2]);
            }
        }

        float mx0 = -1e30f, mx1 = -1e30f;
        #pragma unroll
        for (int a = 0; a < 8; a++) {
            mx0 = fmaxf(mx0, fmaxf(S[a][0], S[a][1]));
            mx1 = fmaxf(mx1, fmaxf(S[a][2], S[a][3]));
        }
        mx0 = fmaxf(mx0, __shfl_xor_sync(0xffffffffu, mx0, 1));
        mx0 = fmaxf(mx0, __shfl_xor_sync(0xffffffffu, mx0, 2));
        mx1 = fmaxf(mx1, __shfl_xor_sync(0xffffffffu, mx1, 1));
        mx1 = fmaxf(mx1, __shfl_xor_sync(0xffffffffu, mx1, 2));
        const float mn0 = fmaxf(m0, mx0);
        const float mn1 = fmaxf(m1, mx1);
        const float corr0 = __expf(m0 - mn0);
        const float corr1 = __expf(m1 - mn1);
        m0 = mn0; m1 = mn1;
        l0 *= corr0; l1 *= corr1;
        #pragma unroll
        for (int a = 0; a < 8; a++) {
            Of[a][0] *= corr0; Of[a][1] *= corr0;
            Of[a][2] *= corr1; Of[a][3] *= corr1;
        }
        float ps0 = 0.f, ps1 = 0.f;
        #pragma unroll
        for (int a = 0; a < 8; a++) {
            S[a][0] = __expf(S[a][0] - m0);
            S[a][1] = __expf(S[a][1] - m0);
            S[a][2] = __expf(S[a][2] - m1);
            S[a][3] = __expf(S[a][3] - m1);
            ps0 += S[a][0] + S[a][1];
            ps1 += S[a][2] + S[a][3];
        }
        l0 += ps0; l1 += ps1;

        uint32_t pa[4][4], pl[4][4];
        #pragma unroll
        for (int kk = 0; kk < 4; kk++) {
            const int a0 = 2 * kk, a1 = 2 * kk + 1;
            pa[kk][0] = pack2bf(S[a0][0], S[a0][1]);
            pa[kk][1] = pack2bf(S[a0][2], S[a0][3]);
            pa[kk][2] = pack2bf(S[a1][0], S[a1][1]);
            pa[kk][3] = pack2bf(S[a1][2], S[a1][3]);
            pl[kk][0] = pack2bf(bfres(S[a0][0]), bfres(S[a0][1]));
            pl[kk][1] = pack2bf(bfres(S[a0][2]), bfres(S[a0][3]));
            pl[kk][2] = pack2bf(bfres(S[a1][0]), bfres(S[a1][1]));
            pl[kk][3] = pack2bf(bfres(S[a1][2]), bfres(S[a1][3]));
        }

        #pragma unroll
        for (int kk = 0; kk < 4; kk++) {
            uint32_t vh[4][4], vl[4][4];
            #pragma unroll
            for (int g = 0; g < 4; g++) {
                const uint32_t voff = (uint32_t)(g * 16 + b_n_l) * AT_STRIDE_B + (kk * 16 + b_k_l) * 2;
                ldsm4(vh[g], VhB + voff);
                ldsm4(vl[g], VlB + voff);
            }
            #pragma unroll
            for (int g = 0; g < 4; g++) {
                mma16816(Of[2*g],   pa[kk], &vh[g][0]);
                mma16816(Of[2*g+1], pa[kk], &vh[g][2]);
                mma16816(Of[2*g],   pl[kk], &vh[g][0]);
                mma16816(Of[2*g+1], pl[kk], &vh[g][2]);
                mma16816(Of[2*g],   pa[kk], &vl[g][0]);
                mma16816(Of[2*g+1], pa[kk], &vl[g][2]);
            }
        }
    }

    l0 += __shfl_xor_sync(0xffffffffu, l0, 1);
    l0 += __shfl_xor_sync(0xffffffffu, l0, 2);
    l1 += __shfl_xor_sync(0xffffffffu, l1, 1);
    l1 += __shfl_xor_sync(0xffffffffu, l1, 2);
    const float inv0 = 1.f / l0;
    const float inv1 = 1.f / l1;

    const int r0 = qt * 64 + w * 16 + (lane >> 2);
    const int r1 = r0 + 8;
    #pragma unroll
    for (int a = 0; a < 8; a++) {
        const int d = h * DHEAD + a * 8 + (lane & 3) * 2;
        const size_t o0 = ((size_t)(b * SEQ + r0)) * DM + d;
        const size_t o1 = ((size_t)(b * SEQ + r1)) * DM + d;
        float f00 = Of[a][0] * inv0, f01 = Of[a][1] * inv0;
        float f10 = Of[a][2] * inv1, f11 = Of[a][3] * inv1;
        *(uint32_t*)&Oh[o0] = pack2bf(f00, f01);
        *(uint32_t*)&Ol[o0] = pack2bf(bfres(f00), bfres(f01));
        *(uint32_t*)&Oh[o1] = pack2bf(f10, f11);
        *(uint32_t*)&Ol[o1] = pack2bf(bfres(f10), bfres(f11));
    }
}

// ---------------------------------------------------------------------------
// Launch
// ---------------------------------------------------------------------------
extern "C" void kernel_launch(void* const* d_in, const int* in_sizes, int n_in,
                              void* d_out, int out_size)
{
    const float* x    = (const float*)d_in[0];
    const float* Wq   = (const float*)d_in[1];
    const float* Wk   = (const float*)d_in[2];
    const float* Wv   = (const float*)d_in[3];
    const float* Wo   = (const float*)d_in[4];
    const float* qn_w = (const float*)d_in[5];
    const float* kn_w = (const float*)d_in[6];
    const float* Mk   = (const float*)d_in[7];
    const float* Mtk  = (const float*)d_in[8];
    const float* Ck   = (const float*)d_in[9];
    const float* Mv   = (const float*)d_in[10];
    const float* Mtv  = (const float*)d_in[11];
    const float* Cv   = (const float*)d_in[12];
    float* out = (float*)d_out;

    float *pQ, *pK, *pV;
    cudaGetSymbolAddress((void**)&pQ, g_Q);
    cudaGetSymbolAddress((void**)&pK, g_K);
    cudaGetSymbolAddress((void**)&pV, g_V);

    __nv_bfloat16 *xh, *xl, *oh, *ol, *wqh, *wql, *woh, *wol;
    __nv_bfloat16 *kbh, *kbl, *vth, *vtl;
    cudaGetSymbolAddress((void**)&xh, g_xh);
    cudaGetSymbolAddress((void**)&xl, g_xl);
    cudaGetSymbolAddress((void**)&oh, g_oh);
    cudaGetSymbolAddress((void**)&ol, g_ol);
    cudaGetSymbolAddress((void**)&wqh, g_wqh);
    cudaGetSymbolAddress((void**)&wql, g_wql);
    cudaGetSymbolAddress((void**)&woh, g_woh);
    cudaGetSymbolAddress((void**)&wol, g_wol);
    cudaGetSymbolAddress((void**)&kbh, g_kbh);
    cudaGetSymbolAddress((void**)&kbl, g_kbl);
    cudaGetSymbolAddress((void**)&vth, g_vth);
    cudaGetSymbolAddress((void**)&vtl, g_vtl);

    static bool inited = false;
    static cudaStream_t sk = 0, sv = 0;
    static cudaEvent_t evRoot = 0, evK = 0, evV = 0;
    if (!inited) {
        cudaStreamCreateWithFlags(&sk, cudaStreamNonBlocking);
        cudaStreamCreateWithFlags(&sv, cudaStreamNonBlocking);
        cudaEventCreateWithFlags(&evRoot, cudaEventDisableTiming);
        cudaEventCreateWithFlags(&evK, cudaEventDisableTiming);
        cudaEventCreateWithFlags(&evV, cudaEventDisableTiming);
        cudaFuncSetAttribute(sgemm_nn,
                             cudaFuncAttributeMaxDynamicSharedMemorySize, SG_SMEM);
        cudaFuncSetAttribute(gemm_mma_kernel,
                             cudaFuncAttributeMaxDynamicSharedMemorySize, MM_SMEM);
        cudaFuncSetAttribute(attn_mma_kernel,
                             cudaFuncAttributeMaxDynamicSharedMemorySize, AT_SMEM);
        inited = true;
    }

    const int splitBlocks = (int)(NELEM / (256 * 4));
    dim3 tgrid(DM / 32, DM / 32);
    dim3 tblock(32, 8);
    dim3 fgrid(DM / BN, MTOK / BM);
    dim3 mgrid(DM / 128, MTOK / 128);
    dim3 vtgrid(SEQ / 32, DHEAD / 32, BATCH * HEADS);

    // fork
    cudaEventRecord(evRoot, 0);
    cudaStreamWaitEvent(sk, evRoot, 0);
    cudaStreamWaitEvent(sv, evRoot, 0);

    // K chain: fp32 GEMM -> fused rmsnorm+quant+split
    sgemm_nn<<<fgrid, 256, SG_SMEM, sk>>>(x, Wk, pK, MTOK, DM, DM);
    kpost_kernel<<<MTOK, 256, 0, sk>>>(pK, kn_w, Mk, Mtk, Ck, kbh, kbl);
    cudaEventRecord(evK, sk);

    // V chain: fp32 GEMM -> quant -> transpose+split
    sgemm_nn<<<fgrid, 256, SG_SMEM, sv>>>(x, Wv, pV, MTOK, DM, DM);
    quant_kernel<<<BATCH * HEADS * SEQ, 64, 0, sv>>>(pV, Mv, Mtv, Cv);
    convert_vt_kernel<<<vtgrid, tblock, 0, sv>>>(pV, vth, vtl);
    cudaEventRecord(evV, sv);

    // Q pipeline on main stream (overlaps with K/V sgemms)
    split_kernel<<<splitBlocks, 256>>>(x, xh, xl);
    tsplit_kernel<<<tgrid, tblock>>>(Wq, wqh, wql);
    tsplit_kernel<<<tgrid, tblock>>>(Wo, woh, wol);
    gemm_mma_kernel<<<mgrid, 256, MM_SMEM>>>(xh, xl, wqh, wql, pQ);
    rmsnorm_kernel<<<MTOK, 256>>>(pQ, qn_w);

    // join
    cudaStreamWaitEvent((cudaStream_t)0, evK, 0);
    cudaStreamWaitEvent((cudaStream_t)0, evV, 0);

    // attention: 64-query CTAs (proven occupancy), fused bf16 output
    attn_mma_kernel<<<dim3(SEQ / 64, HEADS, BATCH), 128, AT_SMEM>>>(
        pQ, kbh, kbl, vth, vtl, oh, ol);

    // O projection
    gemm_mma_kernel<<<mgrid, 256, MM_SMEM>>>(oh, ol, woh, wol, out);
}

// round 11
// speedup vs baseline: 1.0681x; 1.0637x over previous
#include <cuda_runtime.h>
#include <cuda_bf16.h>
#include <math.h>
#include <stdint.h>

#define BATCH 2
#define SEQ 1024
#define HEADS 32
#define DHEAD 64
#define DM 2048
#define MTOK (BATCH * SEQ)      // 2048
#define NGROUPS 22
#define NELEM ((size_t)DM * DM) // 4194304

// ---------------- scratch (device globals; no allocation allowed) ----------
__device__ float g_Q[(size_t)MTOK * DM];
__device__ float g_K[(size_t)MTOK * DM];
__device__ float g_V[(size_t)MTOK * DM];

__device__ __nv_bfloat16 g_xh[NELEM], g_xl[NELEM];
__device__ __nv_bfloat16 g_oh[NELEM], g_ol[NELEM];      // attn output bf16 hi/lo
__device__ __nv_bfloat16 g_wqh[NELEM], g_wql[NELEM];
__device__ __nv_bfloat16 g_woh[NELEM], g_wol[NELEM];
__device__ __nv_bfloat16 g_kbh[NELEM], g_kbl[NELEM];    // K (post-quant) [b*S+s][h*64+d]
__device__ __nv_bfloat16 g_vth[NELEM], g_vtl[NELEM];    // V^T [(b*H+h)*64+d][s]

// ---------------- helpers ---------------------------------------------------
__device__ __forceinline__ uint32_t smem_u32(const void* p) {
    uint32_t a;
    asm("{ .reg .u64 t; cvta.to.shared.u64 t, %1; cvt.u32.u64 %0, t; }"
        : "=r"(a) : "l"(p));
    return a;
}
__device__ __forceinline__ void ldsm4(uint32_t* r, uint32_t addr) {
    asm volatile("ldmatrix.sync.aligned.m8n8.x4.shared.b16 {%0,%1,%2,%3}, [%4];"
                 : "=r"(r[0]), "=r"(r[1]), "=r"(r[2]), "=r"(r[3]) : "r"(addr));
}
__device__ __forceinline__ void mma16816(float* d, const uint32_t* a, const uint32_t* b) {
    asm volatile(
        "mma.sync.aligned.m16n8k16.row.col.f32.bf16.bf16.f32 "
        "{%0,%1,%2,%3}, {%4,%5,%6,%7}, {%8,%9}, {%0,%1,%2,%3};"
        : "+f"(d[0]), "+f"(d[1]), "+f"(d[2]), "+f"(d[3])
        : "r"(a[0]), "r"(a[1]), "r"(a[2]), "r"(a[3]), "r"(b[0]), "r"(b[1]));
}
__device__ __forceinline__ void cp16(uint32_t s, const void* g) {
    uint64_t ga = __cvta_generic_to_global(g);
    asm volatile("cp.async.cg.shared.global [%0], [%1], 16;" :: "r"(s), "l"(ga));
}
__device__ __forceinline__ void cp_commit() {
    asm volatile("cp.async.commit_group;" ::: "memory");
}
template <int N>
__device__ __forceinline__ void cp_wait() {
    asm volatile("cp.async.wait_group %0;" :: "n"(N) : "memory");
}
__device__ __forceinline__ uint32_t pack2bf(float x, float y) {
    __nv_bfloat162 t = __floats2bfloat162_rn(x, y);
    return *(uint32_t*)&t;
}
__device__ __forceinline__ float bfres(float x) {
    return x - __bfloat162float(__float2bfloat16(x));
}
__device__ __forceinline__ void fma_f32x2(uint64_t& d, uint64_t a, uint64_t b) {
    asm("fma.rn.f32x2 %0, %1, %2, %0;" : "+l"(d) : "l"(a), "l"(b));
}
__device__ __forceinline__ uint64_t dup_f32x2(float x) {
    uint64_t r;
    asm("mov.b64 %0, {%1, %1};" : "=l"(r) : "f"(x));
    return r;
}

// ---------------------------------------------------------------------------
// fp32 SGEMM for K,V via packed f32x2 FMA — EXACT R8 version (417us measured).
// Per-element accumulation chain bit-identical to scalar FFMA (k ascending).
// ---------------------------------------------------------------------------
#define BM 128
#define BN 128
#define TM 8
#define TN 8
#define S2_BK 16

__global__ __launch_bounds__(256, 2) void sgemm_nn(
    const float* __restrict__ A, const float* __restrict__ B,
    float* __restrict__ C, int M, int N, int K)
{
    __shared__ float As[2][S2_BK][BM];
    __shared__ float Bs[2][S2_BK][BN];

    const int tid = threadIdx.x;
    const int block_row = blockIdx.y * BM;
    const int block_col = blockIdx.x * BN;

    const int am = tid >> 1;
    const int ak = (tid & 1) * 8;
    const int bk0 = tid >> 5;
    const int bn0 = (tid & 31) * 4;
    const int tr = (tid >> 4) * TM;
    const int tc = (tid & 15) * TN;

    const uint32_t bs_base = smem_u32(&Bs[0][0][0]);

    uint64_t acc2[TM][TN / 2];
    #pragma unroll
    for (int i = 0; i < TM; i++)
        #pragma unroll
        for (int j = 0; j < TN / 2; j++) acc2[i][j] = 0ull;

    float a0[8];
    auto ldgA = [&](int c) {
        float4 u = *(const float4*)&A[(size_t)(block_row + am) * K + c * S2_BK + ak];
        float4 v = *(const float4*)&A[(size_t)(block_row + am) * K + c * S2_BK + ak + 4];
        a0[0] = u.x; a0[1] = u.y; a0[2] = u.z; a0[3] = u.w;
        a0[4] = v.x; a0[5] = v.y; a0[6] = v.z; a0[7] = v.w;
    };
    auto stsA = [&](int buf) {
        #pragma unroll
        for (int i = 0; i < 8; i++) As[buf][ak + i][am] = a0[i];
    };
    auto cpB = [&](int c, int buf) {
        cp16(bs_base + (uint32_t)((buf * S2_BK + bk0) * BN + bn0) * 4,
             &B[(size_t)(c * S2_BK + bk0) * N + block_col + bn0]);
        cp16(bs_base + (uint32_t)((buf * S2_BK + bk0 + 8) * BN + bn0) * 4,
             &B[(size_t)(c * S2_BK + bk0 + 8) * N + block_col + bn0]);
    };

    const int NCH = K / S2_BK;
    ldgA(0);
    cpB(0, 0);
    cp_commit();
    stsA(0);

    for (int c = 0; c < NCH; c++) {
        const int buf = c & 1;
        if (c + 1 < NCH) {
            ldgA(c + 1);
            cpB(c + 1, buf ^ 1);
            cp_commit();
            cp_wait<1>();
        } else {
            cp_wait<0>();
        }
        __syncthreads();

        #pragma unroll
        for (int kk = 0; kk < S2_BK; kk++) {
            uint64_t a2[TM], b2[TN / 2];
            #pragma unroll
            for (int i = 0; i < TM; i++) a2[i] = dup_f32x2(As[buf][kk][tr + i]);
            #pragma unroll
            for (int j = 0; j < TN / 2; j++)
                b2[j] = *(const uint64_t*)&Bs[buf][kk][tc + 2 * j];
            #pragma unroll
            for (int i = 0; i < TM; i++)
                #pragma unroll
                for (int j = 0; j < TN / 2; j++)
                    fma_f32x2(acc2[i][j], a2[i], b2[j]);
        }
        if (c + 1 < NCH) stsA(buf ^ 1);
        __syncthreads();
    }

    #pragma unroll
    for (int i = 0; i < TM; i++) {
        float cvals[TN];
        #pragma unroll
        for (int j = 0; j < TN / 2; j++) {
            float lo, hi;
            asm("mov.b64 {%0, %1}, %2;" : "=f"(lo), "=f"(hi) : "l"(acc2[i][j]));
            cvals[2 * j] = lo;
            cvals[2 * j + 1] = hi;
        }
        #pragma unroll
        for (int j = 0; j < TN; j += 4) {
            float4 cv = make_float4(cvals[j], cvals[j+1], cvals[j+2], cvals[j+3]);
            *(float4*)&C[(size_t)(block_row + tr + i) * N + block_col + tc + j] = cv;
        }
    }
}

// ---------------------------------------------------------------------------
// 2-level split: fp32 -> (hi, lo) bf16, row-major (x, K conv)
// ---------------------------------------------------------------------------
__global__ __launch_bounds__(256) void split_kernel(
    const float* __restrict__ src, __nv_bfloat16* __restrict__ hi,
    __nv_bfloat16* __restrict__ lo)
{
    size_t i = ((size_t)blockIdx.x * 256 + threadIdx.x) * 4;
    float4 v = *(const float4*)(src + i);
    float vv[4] = { v.x, v.y, v.z, v.w };
    __nv_bfloat16 h[4], l[4];
    #pragma unroll
    for (int e = 0; e < 4; e++) {
        h[e] = __float2bfloat16(vv[e]);
        l[e] = __float2bfloat16(vv[e] - __bfloat162float(h[e]));
    }
    *(__nv_bfloat162*)(hi + i)     = { h[0], h[1] };
    *(__nv_bfloat162*)(hi + i + 2) = { h[2], h[3] };
    *(__nv_bfloat162*)(lo + i)     = { l[0], l[1] };
    *(__nv_bfloat162*)(lo + i + 2) = { l[2], l[3] };
}

__global__ __launch_bounds__(256) void tsplit_kernel(
    const float* __restrict__ W, __nv_bfloat16* __restrict__ Th,
    __nv_bfloat16* __restrict__ Tl)
{
    __shared__ float t[32][33];
    const int x = threadIdx.x;
    const int y = threadIdx.y;
    const int n0 = blockIdx.x * 32;
    const int k0 = blockIdx.y * 32;
    #pragma unroll
    for (int i = 0; i < 4; i++)
        t[y + i * 8][x] = W[(size_t)(k0 + y + i * 8) * DM + n0 + x];
    __syncthreads();
    #pragma unroll
    for (int i = 0; i < 4; i++) {
        float v = t[x][y + i * 8];
        __nv_bfloat16 h = __float2bfloat16(v);
        __nv_bfloat16 l = __float2bfloat16(v - __bfloat162float(h));
        size_t o = (size_t)(n0 + y + i * 8) * DM + k0 + x;
        Th[o] = h;
        Tl[o] = l;
    }
}

// Per-(b,h) transpose + split: V[(b*S+s)][h*64+d] -> Vt[(b*H+h)*64+d][s]
__global__ __launch_bounds__(256) void convert_vt_kernel(
    const float* __restrict__ V, __nv_bfloat16* __restrict__ Vh,
    __nv_bfloat16* __restrict__ Vl)
{
    __shared__ float t[32][33];
    const int x = threadIdx.x;
    const int y = threadIdx.y;
    const int s0 = blockIdx.x * 32;
    const int d0 = blockIdx.y * 32;
    const int bh = blockIdx.z;
    const int b = bh >> 5;
    const int h = bh & 31;
    #pragma unroll
    for (int i = 0; i < 4; i++)
        t[y + i * 8][x] = V[(size_t)(b * SEQ + s0 + y + i * 8) * DM + h * DHEAD + d0 + x];
    __syncthreads();
    #pragma unroll
    for (int i = 0; i < 4; i++) {
        float v = t[x][y + i * 8];
        size_t o = (size_t)(bh * DHEAD + d0 + y + i * 8) * SEQ + s0 + x;
        Vh[o] = __float2bfloat16(v);
        Vl[o] = __float2bfloat16(bfres(v));
    }
}

// ---------------------------------------------------------------------------
// bf16 3-term split GEMM via mma.sync (smooth paths: Q, O projections)
// ---------------------------------------------------------------------------
#define MM_STRIDE 80
#define MM_TILE  (128 * MM_STRIDE)
#define MM_BUF   (4 * MM_TILE)
#define MM_SMEM  (2 * MM_BUF)              // 81920 B

__global__ __launch_bounds__(256) void gemm_mma_kernel(
    const __nv_bfloat16* __restrict__ A0, const __nv_bfloat16* __restrict__ A1,
    const __nv_bfloat16* __restrict__ B0, const __nv_bfloat16* __restrict__ B1,
    float* __restrict__ C)
{
    extern __shared__ char sm[];
    const uint32_t sbase = smem_u32(sm);
    const int tid = threadIdx.x;
    const int lane = tid & 31;
    const int wid = tid >> 5;
    const int wm = wid >> 2;
    const int wn = wid & 3;
    const int mrow0 = blockIdx.y * 128;
    const int ncol0 = blockIdx.x * 128;

    const int a_row_l = lane & 15;
    const int a_col_l = (lane >> 4) * 8;
    const int b_n_l   = (lane & 7) | ((lane & 16) >> 1);
    const int b_k_l   = (lane & 8);

    float acc[4][4][4];
    #pragma unroll
    for (int i = 0; i < 4; i++)
        #pragma unroll
        for (int j = 0; j < 4; j++)
            #pragma unroll
            for (int e = 0; e < 4; e++) acc[i][j][e] = 0.f;

    const __nv_bfloat16* srcs[4] = { A0, A1, B0, B1 };

    const int row0 = tid >> 2,  sc0 = tid & 3;
    const int row1 = (tid + 256) >> 2, sc1 = (tid + 256) & 3;

    auto issue = [&](int c, int buf) {
        const int k0 = c * 32;
        #pragma unroll
        for (int t = 0; t < 4; t++) {
            const __nv_bfloat16* src = srcs[t];
            const int rbase = (t < 2) ? mrow0 : ncol0;
            uint32_t sb = sbase + buf * MM_BUF + t * MM_TILE;
            cp16(sb + row0 * MM_STRIDE + sc0 * 16,
                 src + (size_t)(rbase + row0) * DM + k0 + sc0 * 8);
            cp16(sb + row1 * MM_STRIDE + sc1 * 16,
                 src + (size_t)(rbase + row1) * DM + k0 + sc1 * 8);
        }
    };

    issue(0, 0);
    cp_commit();

    const int a_r0 = wm * 64;
    const int b_n0 = wn * 32;

    for (int c = 0; c < DM / 32; c++) {
        const int buf = c & 1;
        if (c + 1 < DM / 32) {
            issue(c + 1, buf ^ 1);
            cp_commit();
            cp_wait<1>();
        } else {
            cp_wait<0>();
        }
        __syncthreads();

        const uint32_t tA0 = sbase + buf * MM_BUF;
        const uint32_t tA1 = tA0 + MM_TILE;
        const uint32_t tB0 = tA0 + 2 * MM_TILE;
        const uint32_t tB1 = tA0 + 3 * MM_TILE;

        #pragma unroll
        for (int ks = 0; ks < 32; ks += 16) {
            const uint32_t aoff = (uint32_t)(a_r0 + a_row_l) * MM_STRIDE + (ks + a_col_l) * 2;
            const uint32_t boffA = (uint32_t)(b_n0 + b_n_l) * MM_STRIDE + (ks + b_k_l) * 2;
            const uint32_t boffB = (uint32_t)(b_n0 + 16 + b_n_l) * MM_STRIDE + (ks + b_k_l) * 2;

            uint32_t a0f[4][4], a1f[4][4], b0f[2][4], b1f[2][4];

            ldsm4(b0f[0], tB0 + boffA);
            ldsm4(b0f[1], tB0 + boffB);
            #pragma unroll
            for (int ma = 0; ma < 4; ma++)
                ldsm4(a0f[ma], tA0 + aoff + ma * 16 * MM_STRIDE);
            #pragma unroll
            for (int ma = 0; ma < 4; ma++)
                #pragma unroll
                for (int na = 0; na < 4; na++)
                    mma16816(acc[ma][na], a0f[ma], &b0f[na >> 1][(na & 1) * 2]);

            ldsm4(b1f[0], tB1 + boffA);
            ldsm4(b1f[1], tB1 + boffB);
            #pragma unroll
            for (int ma = 0; ma < 4; ma++)
                #pragma unroll
                for (int na = 0; na < 4; na++)
                    mma16816(acc[ma][na], a0f[ma], &b1f[na >> 1][(na & 1) * 2]);

            #pragma unroll
            for (int ma = 0; ma < 4; ma++)
                ldsm4(a1f[ma], tA1 + aoff + ma * 16 * MM_STRIDE);
            #pragma unroll
            for (int ma = 0; ma < 4; ma++)
                #pragma unroll
                for (int na = 0; na < 4; na++)
                    mma16816(acc[ma][na], a1f[ma], &b0f[na >> 1][(na & 1) * 2]);
        }
        __syncthreads();
    }

    #pragma unroll
    for (int ma = 0; ma < 4; ma++) {
        #pragma unroll
        for (int na = 0; na < 4; na++) {
            const int r = mrow0 + wm * 64 + ma * 16 + (lane >> 2);
            const int cc = ncol0 + wn * 32 + na * 8 + (lane & 3) * 2;
            *(float2*)&C[(size_t)r * DM + cc] = make_float2(acc[ma][na][0], acc[ma][na][1]);
            *(float2*)&C[(size_t)(r + 8) * DM + cc] = make_float2(acc[ma][na][2], acc[ma][na][3]);
        }
    }
}

// ---------------------------------------------------------------------------
// RMSNorm in-place over rows of length DM
// ---------------------------------------------------------------------------
__global__ __launch_bounds__(256) void rmsnorm_kernel(
    float* __restrict__ y, const float* __restrict__ w)
{
    __shared__ float red[256];
    const int t = threadIdx.x;
    float* p = y + (size_t)blockIdx.x * DM;

    float ss = 0.f;
    for (int i = t; i < DM; i += 256) { float v = p[i]; ss += v * v; }
    red[t] = ss;
    __syncthreads();
    for (int o = 128; o > 0; o >>= 1) {
        if (t < o) red[t] += red[t + o];
        __syncthreads();
    }
    const float r = rsqrtf(red[0] / (float)DM + 1e-6f);
    for (int i = t; i < DM; i += 256) p[i] = p[i] * r * w[i];
}

// ---------------------------------------------------------------------------
// RotorQuant roundtrip, in-place. One 64-thread block per (b,h,s) vector.
// ---------------------------------------------------------------------------
__global__ __launch_bounds__(64) void quant_kernel(
    float* __restrict__ data,
    const float* __restrict__ Mg, const float* __restrict__ Mtg,
    const float* __restrict__ Cg)
{
    __shared__ float xs[66];
    __shared__ float ys[66];
    __shared__ float red[64];
    __shared__ float Cs[8];
    __shared__ float Ms[NGROUPS * 9];
    __shared__ float Mts[NGROUPS * 9];

    const int t = threadIdx.x;
    const int idx = blockIdx.x;
    const int s = idx & (SEQ - 1);
    const int h = (idx >> 10) & (HEADS - 1);
    const int b = idx >> 15;

    float* p = data + ((size_t)(b * SEQ + s)) * DM + h * DHEAD;

    for (int i = t; i < NGROUPS * 9; i += 64) { Ms[i] = Mg[i]; Mts[i] = Mtg[i]; }
    if (t < 8) Cs[t] = Cg[t];

    const float v = p[t];
    red[t] = v * v;
    __syncthreads();
    for (int o = 32; o > 0; o >>= 1) {
        if (t < o) red[t] += red[t + o];
        __syncthreads();
    }
    const float norm = fmaxf(sqrtf(red[0]), 1e-8f);
    xs[t] = v / norm;
    if (t < 2) xs[64 + t] = 0.f;
    __syncthreads();

    if (t < NGROUPS) {
        const float g0 = xs[3 * t + 0];
        const float g1 = xs[3 * t + 1];
        const float g2 = xs[3 * t + 2];
        const float* m = Ms + t * 9;
        float r0 = g0 * m[0] + g1 * m[3] + g2 * m[6];
        float r1 = g0 * m[1] + g1 * m[4] + g2 * m[7];
        float r2 = g0 * m[2] + g1 * m[5] + g2 * m[8];

        const float C0 = Cs[0];
        const float invstep = 1.f / (Cs[1] - Cs[0]);
        float q[3];
        float rr[3] = { r0, r1, r2 };
        #pragma unroll
        for (int e = 0; e < 3; e++) {
            int i = (int)floorf((rr[e] - C0) * invstep);
            i = max(0, min(6, i));
            float d0 = fabsf(rr[e] - Cs[i]);
            float d1 = fabsf(rr[e] - Cs[i + 1]);
            q[e] = (d0 <= d1) ? Cs[i] : Cs[i + 1];
        }

        const float* mt2 = Mts + t * 9;
        ys[3 * t + 0] = q[0] * mt2[0] + q[1] * mt2[3] + q[2] * mt2[6];
        ys[3 * t + 1] = q[0] * mt2[1] + q[1] * mt2[4] + q[2] * mt2[7];
        ys[3 * t + 2] = q[0] * mt2[2] + q[1] * mt2[5] + q[2] * mt2[8];
    }
    __syncthreads();
    p[t] = ys[t] * norm;
}

// ---------------------------------------------------------------------------
// Tensor-core flash attention: 64 queries/CTA (proven R8 shape),
// K/V bf16 hi/lo pre-converted, cp.async double-buffered,
// fused bf16 hi/lo output epilogue (kept from R9 — traffic-positive).
// ---------------------------------------------------------------------------
#define AT_STRIDE_B 144
#define AT_TILE (64 * AT_STRIDE_B)          // 9216 B
#define AT_SMEM (10 * AT_TILE)              // 92160 B

__global__ __launch_bounds__(128) void attn_mma_kernel(
    const float* __restrict__ Q,
    const __nv_bfloat16* __restrict__ Kbh, const __nv_bfloat16* __restrict__ Kbl,
    const __nv_bfloat16* __restrict__ Vth, const __nv_bfloat16* __restrict__ Vtl,
    __nv_bfloat16* __restrict__ Oh, __nv_bfloat16* __restrict__ Ol)
{
    extern __shared__ char smat[];
    const uint32_t sb = smem_u32(smat);
    const uint32_t QhB = sb;
    const uint32_t QlB = sb + AT_TILE;

    const int tid = threadIdx.x;
    const int lane = tid & 31;
    const int w = tid >> 5;
    const int qt = blockIdx.x;
    const int h = blockIdx.y;
    const int b = blockIdx.z;
    const int bh = b * HEADS + h;

    const int a_row_l = lane & 15;
    const int a_col_l = (lane >> 4) * 8;
    const int b_n_l   = (lane & 7) | ((lane & 16) >> 1);
    const int b_k_l   = (lane & 8);

    // ---- convert Q tile (scaled by 1/8) to bf16 hi/lo (once) ----
    {
        const int cr = tid >> 1;
        const int cd = (tid & 1) * 32;
        const float* qrow = Q + ((size_t)(b * SEQ + qt * 64 + cr)) * DM + h * DHEAD + cd;
        #pragma unroll
        for (int s = 0; s < 8; s++) {
            float4 v = *(const float4*)(qrow + s * 4);
            float f[4] = { v.x * 0.125f, v.y * 0.125f, v.z * 0.125f, v.w * 0.125f };
            uint32_t off = (uint32_t)cr * AT_STRIDE_B + (cd + s * 4) * 2;
            *(uint32_t*)(smat + off)               = pack2bf(f[0], f[1]);
            *(uint32_t*)(smat + off + 4)           = pack2bf(f[2], f[3]);
            *(uint32_t*)(smat + AT_TILE + off)     = pack2bf(bfres(f[0]), bfres(f[1]));
            *(uint32_t*)(smat + AT_TILE + off + 4) = pack2bf(bfres(f[2]), bfres(f[3]));
        }
    }

    auto prefetch = [&](int kt, int buf) {
        const uint32_t base = sb + 2 * AT_TILE + buf * 4 * AT_TILE;
        const __nv_bfloat16* kh = Kbh + ((size_t)(b * SEQ + kt * 64)) * DM + h * DHEAD;
        const __nv_bfloat16* kl = Kbl + ((size_t)(b * SEQ + kt * 64)) * DM + h * DHEAD;
        const __nv_bfloat16* vh = Vth + (size_t)bh * DHEAD * SEQ + kt * 64;
        const __nv_bfloat16* vl = Vtl + (size_t)bh * DHEAD * SEQ + kt * 64;
        #pragma unroll
        for (int i = 0; i < 4; i++) {
            const int idx = tid + i * 128;
            const int r = idx >> 3, sg = idx & 7;
            const uint32_t dst = base + (uint32_t)r * AT_STRIDE_B + sg * 16;
            cp16(dst,               kh + (size_t)r * DM + sg * 8);
            cp16(dst + AT_TILE,     kl + (size_t)r * DM + sg * 8);
            cp16(dst + 2 * AT_TILE, vh + (size_t)r * SEQ + sg * 8);
            cp16(dst + 3 * AT_TILE, vl + (size_t)r * SEQ + sg * 8);
        }
    };

    float S[8][4], Of[8][4];
    #pragma unroll
    for (int a = 0; a < 8; a++)
        #pragma unroll
        for (int e = 0; e < 4; e++) Of[a][e] = 0.f;
    float m0 = -1e30f, m1 = -1e30f, l0 = 0.f, l1 = 0.f;

    prefetch(0, 0);
    cp_commit();

    for (int kt = 0; kt < SEQ / 64; kt++) {
        const int buf = kt & 1;
        __syncthreads();
        if (kt + 1 < SEQ / 64) {
            prefetch(kt + 1, buf ^ 1);
            cp_commit();
            cp_wait<1>();
        } else {
            cp_wait<0>();
        }
        __syncthreads();

        const uint32_t KhB = sb + 2 * AT_TILE + buf * 4 * AT_TILE;
        const uint32_t KlB = KhB + AT_TILE;
        const uint32_t VhB = KhB + 2 * AT_TILE;
        const uint32_t VlB = KhB + 3 * AT_TILE;

        #pragma unroll
        for (int a = 0; a < 8; a++)
            #pragma unroll
            for (int e = 0; e < 4; e++) S[a][e] = 0.f;

        #pragma unroll
        for (int kd = 0; kd < 4; kd++) {
            uint32_t qh[4], ql[4], kh[4][4], kl[4][4];
            const uint32_t qoff = (uint32_t)(w * 16 + a_row_l) * AT_STRIDE_B + (kd * 16 + a_col_l) * 2;
            ldsm4(qh, QhB + qoff);
            ldsm4(ql, QlB + qoff);
            #pragma unroll
            for (int g = 0; g < 4; g++) {
                const uint32_t koff = (uint32_t)(g * 16 + b_n_l) * AT_STRIDE_B + (kd * 16 + b_k_l) * 2;
                ldsm4(kh[g], KhB + koff);
                ldsm4(kl[g], KlB + koff);
            }
            #pragma unroll
            for (int g = 0; g < 4; g++) {
                mma16816(S[2*g],   qh, &kh[g][0]);
                mma16816(S[2*g+1], qh, &kh[g][2]);
                mma16816(S[2*g],   ql, &kh[g][0]);
                mma16816(S[2*g+1], ql, &kh[g][2]);
                mma16816(S[2*g],   qh, &kl[g][0]);
                mma16816(S[2*g+1], qh, &kl[g][2]);
            }
        }

        float mx0 = -1e30f, mx1 = -1e30f;
        #pragma unroll
        for (int a = 0; a < 8; a++) {
            mx0 = fmaxf(mx0, fmaxf(S[a][0], S[a][1]));
            mx1 = fmaxf(mx1, fmaxf(S[a][2], S[a][3]));
        }
        mx0 = fmaxf(mx0, __shfl_xor_sync(0xffffffffu, mx0, 1));
        mx0 = fmaxf(mx0, __shfl_xor_sync(0xffffffffu, mx0, 2));
        mx1 = fmaxf(mx1, __shfl_xor_sync(0xffffffffu, mx1, 1));
        mx1 = fmaxf(mx1, __shfl_xor_sync(0xffffffffu, mx1, 2));
        const float mn0 = fmaxf(m0, mx0);
        const float mn1 = fmaxf(m1, mx1);
        const float corr0 = __expf(m0 - mn0);
        const float corr1 = __expf(m1 - mn1);
        m0 = mn0; m1 = mn1;
        l0 *= corr0; l1 *= corr1;
        #pragma unroll
        for (int a = 0; a < 8; a++) {
            Of[a][0] *= corr0; Of[a][1] *= corr0;
            Of[a][2] *= corr1; Of[a][3] *= corr1;
        }
        float ps0 = 0.f, ps1 = 0.f;
        #pragma unroll
        for (int a = 0; a < 8; a++) {
            S[a][0] = __expf(S[a][0] - m0);
            S[a][1] = __expf(S[a][1] - m0);
            S[a][2] = __expf(S[a][2] - m1);
            S[a][3] = __expf(S[a][3] - m1);
            ps0 += S[a][0] + S[a][1];
            ps1 += S[a][2] + S[a][3];
        }
        l0 += ps0; l1 += ps1;

        uint32_t pa[4][4], pl[4][4];
        #pragma unroll
        for (int kk = 0; kk < 4; kk++) {
            const int a0 = 2 * kk, a1 = 2 * kk + 1;
            pa[kk][0] = pack2bf(S[a0][0], S[a0][1]);
            pa[kk][1] = pack2bf(S[a0][2], S[a0][3]);
            pa[kk][2] = pack2bf(S[a1][0], S[a1][1]);
            pa[kk][3] = pack2bf(S[a1][2], S[a1][3]);
            pl[kk][0] = pack2bf(bfres(S[a0][0]), bfres(S[a0][1]));
            pl[kk][1] = pack2bf(bfres(S[a0][2]), bfres(S[a0][3]));
            pl[kk][2] = pack2bf(bfres(S[a1][0]), bfres(S[a1][1]));
            pl[kk][3] = pack2bf(bfres(S[a1][2]), bfres(S[a1][3]));
        }

        #pragma unroll
        for (int kk = 0; kk < 4; kk++) {
            uint32_t vh[4][4], vl[4][4];
            #pragma unroll
            for (int g = 0; g < 4; g++) {
                const uint32_t voff = (uint32_t)(g * 16 + b_n_l) * AT_STRIDE_B + (kk * 16 + b_k_l) * 2;
                ldsm4(vh[g], VhB + voff);
                ldsm4(vl[g], VlB + voff);
            }
            #pragma unroll
            for (int g = 0; g < 4; g++) {
                mma16816(Of[2*g],   pa[kk], &vh[g][0]);
                mma16816(Of[2*g+1], pa[kk], &vh[g][2]);
                mma16816(Of[2*g],   pl[kk], &vh[g][0]);
                mma16816(Of[2*g+1], pl[kk], &vh[g][2]);
                mma16816(Of[2*g],   pa[kk], &vl[g][0]);
                mma16816(Of[2*g+1], pa[kk], &vl[g][2]);
            }
        }
    }

    l0 += __shfl_xor_sync(0xffffffffu, l0, 1);
    l0 += __shfl_xor_sync(0xffffffffu, l0, 2);
    l1 += __shfl_xor_sync(0xffffffffu, l1, 1);
    l1 += __shfl_xor_sync(0xffffffffu, l1, 2);
    const float inv0 = 1.f / l0;
    const float inv1 = 1.f / l1;

    const int r0 = qt * 64 + w * 16 + (lane >> 2);
    const int r1 = r0 + 8;
    #pragma unroll
    for (int a = 0; a < 8; a++) {
        const int d = h * DHEAD + a * 8 + (lane & 3) * 2;
        const size_t o0 = ((size_t)(b * SEQ + r0)) * DM + d;
        const size_t o1 = ((size_t)(b * SEQ + r1)) * DM + d;
        float f00 = Of[a][0] * inv0, f01 = Of[a][1] * inv0;
        float f10 = Of[a][2] * inv1, f11 = Of[a][3] * inv1;
        *(uint32_t*)&Oh[o0] = pack2bf(f00, f01);
        *(uint32_t*)&Ol[o0] = pack2bf(bfres(f00), bfres(f01));
        *(uint32_t*)&Oh[o1] = pack2bf(f10, f11);
        *(uint32_t*)&Ol[o1] = pack2bf(bfres(f10), bfres(f11));
    }
}

// ---------------------------------------------------------------------------
// Launch: fork K-chain and V-chain onto side streams, Q pipeline on main;
// join before attention.
// ---------------------------------------------------------------------------
extern "C" void kernel_launch(void* const* d_in, const int* in_sizes, int n_in,
                              void* d_out, int out_size)
{
    const float* x    = (const float*)d_in[0];
    const float* Wq   = (const float*)d_in[1];
    const float* Wk   = (const float*)d_in[2];
    const float* Wv   = (const float*)d_in[3];
    const float* Wo   = (const float*)d_in[4];
    const float* qn_w = (const float*)d_in[5];
    const float* kn_w = (const float*)d_in[6];
    const float* Mk   = (const float*)d_in[7];
    const float* Mtk  = (const float*)d_in[8];
    const float* Ck   = (const float*)d_in[9];
    const float* Mv   = (const float*)d_in[10];
    const float* Mtv  = (const float*)d_in[11];
    const float* Cv   = (const float*)d_in[12];
    float* out = (float*)d_out;

    float *pQ, *pK, *pV;
    cudaGetSymbolAddress((void**)&pQ, g_Q);
    cudaGetSymbolAddress((void**)&pK, g_K);
    cudaGetSymbolAddress((void**)&pV, g_V);

    __nv_bfloat16 *xh, *xl, *oh, *ol, *wqh, *wql, *woh, *wol;
    __nv_bfloat16 *kbh, *kbl, *vth, *vtl;
    cudaGetSymbolAddress((void**)&xh, g_xh);
    cudaGetSymbolAddress((void**)&xl, g_xl);
    cudaGetSymbolAddress((void**)&oh, g_oh);
    cudaGetSymbolAddress((void**)&ol, g_ol);
    cudaGetSymbolAddress((void**)&wqh, g_wqh);
    cudaGetSymbolAddress((void**)&wql, g_wql);
    cudaGetSymbolAddress((void**)&woh, g_woh);
    cudaGetSymbolAddress((void**)&wol, g_wol);
    cudaGetSymbolAddress((void**)&kbh, g_kbh);
    cudaGetSymbolAddress((void**)&kbl, g_kbl);
    cudaGetSymbolAddress((void**)&vth, g_vth);
    cudaGetSymbolAddress((void**)&vtl, g_vtl);

    static bool inited = false;
    static cudaStream_t sk = 0, sv = 0;
    static cudaEvent_t evRoot = 0, evK = 0, evV = 0;
    if (!inited) {
        cudaStreamCreateWithFlags(&sk, cudaStreamNonBlocking);
        cudaStreamCreateWithFlags(&sv, cudaStreamNonBlocking);
        cudaEventCreateWithFlags(&evRoot, cudaEventDisableTiming);
        cudaEventCreateWithFlags(&evK, cudaEventDisableTiming);
        cudaEventCreateWithFlags(&evV, cudaEventDisableTiming);
        cudaFuncSetAttribute(gemm_mma_kernel,
                             cudaFuncAttributeMaxDynamicSharedMemorySize, MM_SMEM);
        cudaFuncSetAttribute(attn_mma_kernel,
                             cudaFuncAttributeMaxDynamicSharedMemorySize, AT_SMEM);
        inited = true;
    }

    const int splitBlocks = (int)(NELEM / (256 * 4));
    dim3 tgrid(DM / 32, DM / 32);
    dim3 tblock(32, 8);
    dim3 fgrid(DM / BN, MTOK / BM);
    dim3 mgrid(DM / 128, MTOK / 128);
    dim3 vtgrid(SEQ / 32, DHEAD / 32, BATCH * HEADS);

    // fork
    cudaEventRecord(evRoot, 0);
    cudaStreamWaitEvent(sk, evRoot, 0);
    cudaStreamWaitEvent(sv, evRoot, 0);

    // K chain (R8 structure): fp32 GEMM -> rmsnorm -> quant -> split
    sgemm_nn<<<fgrid, 256, 0, sk>>>(x, Wk, pK, MTOK, DM, DM);
    rmsnorm_kernel<<<MTOK, 256, 0, sk>>>(pK, kn_w);
    quant_kernel<<<BATCH * HEADS * SEQ, 64, 0, sk>>>(pK, Mk, Mtk, Ck);
    split_kernel<<<splitBlocks, 256, 0, sk>>>(pK, kbh, kbl);
    cudaEventRecord(evK, sk);

    // V chain: fp32 GEMM -> quant -> transpose+split
    sgemm_nn<<<fgrid, 256, 0, sv>>>(x, Wv, pV, MTOK, DM, DM);
    quant_kernel<<<BATCH * HEADS * SEQ, 64, 0, sv>>>(pV, Mv, Mtv, Cv);
    convert_vt_kernel<<<vtgrid, tblock, 0, sv>>>(pV, vth, vtl);
    cudaEventRecord(evV, sv);

    // Q pipeline on main stream (overlaps with K/V sgemms)
    split_kernel<<<splitBlocks, 256>>>(x, xh, xl);
    tsplit_kernel<<<tgrid, tblock>>>(Wq, wqh, wql);
    tsplit_kernel<<<tgrid, tblock>>>(Wo, woh, wol);
    gemm_mma_kernel<<<mgrid, 256, MM_SMEM>>>(xh, xl, wqh, wql, pQ);
    rmsnorm_kernel<<<MTOK, 256>>>(pQ, qn_w);

    // join
    cudaStreamWaitEvent((cudaStream_t)0, evK, 0);
    cudaStreamWaitEvent((cudaStream_t)0, evV, 0);

    // attention: 64-query CTAs, fused bf16 hi/lo output
    attn_mma_kernel<<<dim3(SEQ / 64, HEADS, BATCH), 128, AT_SMEM>>>(
        pQ, kbh, kbl, vth, vtl, oh, ol);

    // O projection (reads bf16 hi/lo directly — no split pass)
    gemm_mma_kernel<<<mgrid, 256, MM_SMEM>>>(oh, ol, woh, wol, out);
}